// round 10
// baseline (speedup 1.0000x reference)
#include <cuda_runtime.h>
#include <cuda_bf16.h>
#include <math.h>

// ---------------- static problem config ----------------
#define BB   64
#define LLEN 1024
#define CIN  16
#define DD   256
#define HH   8
#define DFF  1024
#define HSZ  256
#define NLAY 2
#define TOPK 20
#define MAW  25   // moving average window

// ---------------- device scratch (no allocs allowed) ----------------
__device__ __align__(16) float g_h1 [BB*LLEN*DD];            // conv1 out
__device__ __align__(16) float g_enc[BB*LLEN*DD];            // encoder state
__device__ __align__(16) float g_q  [BB*LLEN*DD];
__device__ __align__(16) float g_k  [BB*LLEN*DD];
__device__ __align__(16) float g_v  [BB*LLEN*DD];
__device__ __align__(16) float g_ac [BB*LLEN*DD];            // autocorr agg out
__device__ __align__(16) float g_xs [BB*LLEN*DD];            // x (pre-decomp) / conv2 out
__device__ __align__(16) float g_xd [BB*LLEN*DD];            // x after decomp
__device__ __align__(16) float g_big[BB*LLEN*DFF];           // FFN hidden
__device__ __align__(16) float g_rp [BB*LLEN];               // correlation sums per tau
__device__ int   g_del[BB*TOPK];
__device__ float g_w  [BB*TOPK];
__device__ __align__(16) float g_emb[BB*HSZ];
__device__ __align__(16) float g_final[BB*(NLAY*DD+HSZ)];    // [64][768]
__device__ __align__(16) float g_o1[BB*HSZ];
__device__ __align__(16) float g_o2[BB*HSZ];
__device__ __align__(16) float g_w2t[768*256];               // conv2 weights as [K=768][N=256]

// ---------------- epilogue flags ----------------
#define EPI_BIAS 1
#define EPI_RELU 2
#define EPI_GELU 4
#define EPI_RES  8
#define EPI_GRAM 16   // no C tile write; reduce wrapped diagonals into C (=rp+b*1024)

__device__ __forceinline__ unsigned f2tf(float f) {
    unsigned u;
    asm("cvt.rna.tf32.f32 %0, %1;" : "=r"(u) : "f"(f));
    return u;
}

__device__ __forceinline__ void mma_tf32(float* c, const unsigned* a, const unsigned* b) {
    asm volatile(
        "mma.sync.aligned.m16n8k8.row.col.f32.tf32.tf32.f32 "
        "{%0,%1,%2,%3}, {%4,%5,%6,%7}, {%8,%9}, {%0,%1,%2,%3};\n"
        : "+f"(c[0]), "+f"(c[1]), "+f"(c[2]), "+f"(c[3])
        : "r"(a[0]), "r"(a[1]), "r"(a[2]), "r"(a[3]), "r"(b[0]), "r"(b[1]));
}

// 16B cp.async with zero-fill predicate (src_size = 0 -> all zeros)
__device__ __forceinline__ void cp16(unsigned smem_addr, const void* gptr, bool pred) {
    int sz = pred ? 16 : 0;
    asm volatile("cp.async.cg.shared.global [%0], [%1], 16, %2;\n"
                 :: "r"(smem_addr), "l"(gptr), "r"(sz));
}
__device__ __forceinline__ void cp_commit() {
    asm volatile("cp.async.commit_group;\n");
}

// =====================================================================
// tf32 tensor-core GEMM, 128x128x16 tile, 256 threads (8 warps),
// warp tile 64x32 (warps 2 x 4), mma m16n8k8.
// 4-stage cp.async pipeline (dynamic smem, 84.5KB/block): copies for
// tiles it+1..it+3 are in flight while tile it computes; ONE barrier
// per iteration; wait_group 2 keeps 2 newest groups outstanding.
// An (empty) commit_group is issued every iteration so the group
// counting stays exact at the loop tail.
// Tiles live in smem as RAW fp32; tf32 rounding (cvt.rna) is applied
// at fragment load -- identical math to converting at store time.
//
// smem layouts (conflict-free fragment reads + 16B cp.async chunks):
//   A (and TB-true B): [row][k], row stride 20 floats
//   TB-false B:        [k][n],   k stride 136 floats
//
// AMODE: 0 = normal A [M,K]; 1 = conv2 shifted-A (A is h1[L,256], K=768,
//        k-chunk j in {0,1,2} reads row l+j-1 with zero padding).
// TB: false -> B[K,N] row-major; true -> B[N,K] row-major.
// Batched via gridDim.z with element strides sA,sB,sC.
// EPI_GRAM: instead of writing C[M,N], reduce tile into wrapped-diagonal
//           sums: C[(m-n)&1023] += acc  (C is rp + b*1024, pre-zeroed).
// =====================================================================
#define ASTRIDE 20
#define ASTAGE  (128 * ASTRIDE)   // 2560 floats per stage
#define BSTAGE  2720              // max(128*20, 16*136) floats per stage
#define NSTAGE  4
#define TG_DYN_BYTES (NSTAGE * (ASTAGE + BSTAGE) * 4)   // 84480

template<int AMODE, bool TB, int EPI>
__global__ __launch_bounds__(256) void tgemm128(
    const float* __restrict__ A, const float* __restrict__ B,
    const float* __restrict__ bias, const float* __restrict__ res,
    float* __restrict__ C, int M, int N, int K,
    long long sA, long long sB, long long sC)
{
    extern __shared__ float dynsm[];
    float* Asm = dynsm;                      // NSTAGE * ASTAGE
    float* Bsm = dynsm + NSTAGE * ASTAGE;    // NSTAGE * BSTAGE
    __shared__ float sdiag[256];
    long long bz = blockIdx.z;
    A += bz * sA;  B += bz * sB;  C += bz * sC;
    if (EPI & EPI_RES) res += bz * sC;

    int m0 = blockIdx.y * 128, n0 = blockIdx.x * 128;
    int t = threadIdx.x;
    int wid = t >> 5, lane = t & 31;
    int g = lane >> 2, t4 = lane & 3;
    int wm = (wid & 1) * 64;
    int wn = (wid >> 1) * 32;

    unsigned sA_u = (unsigned)__cvta_generic_to_shared(Asm);
    unsigned sB_u = (unsigned)__cvta_generic_to_shared(Bsm);

    float acc[4][4][4];
    #pragma unroll
    for (int mi = 0; mi < 4; mi++)
        #pragma unroll
        for (int ni = 0; ni < 4; ni++)
            #pragma unroll
            for (int r = 0; r < 4; r++) acc[mi][ni][r] = 0.f;

    // per-thread copy assignment (2 x 16B chunks for A, 2 for B)
    const int arow = t >> 1, ac0 = (t & 1) * 8;
    int brow, bc0;
    if (TB) { brow = t >> 1;  bc0 = (t & 1) * 8; }   // [n][k]
    else    { brow = t >> 4;  bc0 = (t & 15) * 8; }  // [k][n]

#define ISSUE_COPY(ST, K0)                                                     \
    {                                                                          \
        unsigned as = sA_u + ((ST) * ASTAGE + arow * ASTRIDE + ac0) * 4;       \
        if (AMODE == 0) {                                                      \
            const float* gp = A + (long long)(m0 + arow) * K + (K0) + ac0;     \
            cp16(as, gp, true);  cp16(as + 16, gp + 4, true);                  \
        } else {                                                               \
            int kk = (K0) + ac0;                                               \
            int sft = kk >> 8;                                                 \
            int cc  = kk & 255;                                                \
            int ll  = m0 + arow + sft - 1;                                     \
            bool ok = (ll >= 0 && ll < LLEN);                                  \
            const float* gp = ok ? (A + (long long)ll * 256 + cc) : A;         \
            cp16(as, gp, ok);  cp16(as + 16, gp + 4, ok);                      \
        }                                                                      \
        if (TB) {                                                              \
            unsigned bs = sB_u + ((ST) * BSTAGE + brow * ASTRIDE + bc0) * 4;   \
            const float* gp = B + (long long)(n0 + brow) * K + (K0) + bc0;     \
            cp16(bs, gp, true);  cp16(bs + 16, gp + 4, true);                  \
        } else {                                                               \
            unsigned bs = sB_u + ((ST) * BSTAGE + brow * 136 + bc0) * 4;       \
            const float* gp = B + (long long)((K0) + brow) * N + n0 + bc0;     \
            cp16(bs, gp, true);  cp16(bs + 16, gp + 4, true);                  \
        }                                                                      \
    }

    const int KT = K / 16;
    // prologue: issue NSTAGE-1 tiles (KT >= 16 for all our shapes)
    #pragma unroll
    for (int p = 0; p < NSTAGE - 1; p++) {
        ISSUE_COPY(p, p * 16);
        cp_commit();
    }

    for (int it = 0; it < KT; it++) {
        // wait until <=2 newest groups pending -> tile `it` is resident
        asm volatile("cp.async.wait_group 2;\n");
        __syncthreads();   // data visible to all warps; also guards the
                           // overwrite of stage (it-1)%4 issued below

        int nt = it + NSTAGE - 1;
        if (nt < KT) ISSUE_COPY(nt & (NSTAGE - 1), nt * 16);
        cp_commit();       // empty commit at tail keeps counting exact

        const float* As  = Asm + (it & (NSTAGE - 1)) * ASTAGE;
        const float* Bsr = Bsm + (it & (NSTAGE - 1)) * BSTAGE;

        #pragma unroll
        for (int ks = 0; ks < 2; ks++) {
            int k0f = ks * 8 + t4;
            unsigned afr[4][4], bfr[4][2];
            #pragma unroll
            for (int mi = 0; mi < 4; mi++) {
                int mr = wm + mi * 16 + g;
                afr[mi][0] = f2tf(As[mr * ASTRIDE + k0f]);
                afr[mi][1] = f2tf(As[(mr + 8) * ASTRIDE + k0f]);
                afr[mi][2] = f2tf(As[mr * ASTRIDE + k0f + 4]);
                afr[mi][3] = f2tf(As[(mr + 8) * ASTRIDE + k0f + 4]);
            }
            #pragma unroll
            for (int ni = 0; ni < 4; ni++) {
                int nc = wn + ni * 8 + g;
                if (TB) {
                    bfr[ni][0] = f2tf(Bsr[nc * ASTRIDE + k0f]);
                    bfr[ni][1] = f2tf(Bsr[nc * ASTRIDE + k0f + 4]);
                } else {
                    bfr[ni][0] = f2tf(Bsr[k0f * 136 + nc]);
                    bfr[ni][1] = f2tf(Bsr[(k0f + 4) * 136 + nc]);
                }
            }
            #pragma unroll
            for (int mi = 0; mi < 4; mi++)
                #pragma unroll
                for (int ni = 0; ni < 4; ni++)
                    mma_tf32(acc[mi][ni], afr[mi], bfr[ni]);
        }
    }
#undef ISSUE_COPY

    __syncthreads();

    if (EPI & EPI_GRAM) {
        // wrapped-diagonal reduction of this 128x128 tile into tau bins.
        sdiag[t] = 0.f;
        __syncthreads();
        #pragma unroll
        for (int mi = 0; mi < 4; mi++) {
            #pragma unroll
            for (int ni = 0; ni < 4; ni++) {
                int li0 = wm + mi * 16 + g;
                int lj0 = wn + ni * 8 + t4 * 2;
                #pragma unroll
                for (int half = 0; half < 2; half++) {
                    int li = li0 + half * 8;
                    atomicAdd(&sdiag[li - lj0 + 127],     acc[mi][ni][half * 2 + 0]);
                    atomicAdd(&sdiag[li - (lj0+1) + 127], acc[mi][ni][half * 2 + 1]);
                }
            }
        }
        __syncthreads();
        if (t < 255) {
            int tau = (m0 - n0 - 127 + t) & (LLEN - 1);
            atomicAdd(&C[tau], sdiag[t]);
        }
        return;
    }

    #pragma unroll
    for (int mi = 0; mi < 4; mi++) {
        #pragma unroll
        for (int ni = 0; ni < 4; ni++) {
            long long row0 = m0 + wm + mi * 16 + g;
            int col0 = n0 + wn + ni * 8 + t4 * 2;
            #pragma unroll
            for (int half = 0; half < 2; half++) {
                long long gm = row0 + half * 8;
                float v0 = acc[mi][ni][half * 2 + 0];
                float v1 = acc[mi][ni][half * 2 + 1];
                if (EPI & EPI_BIAS) { v0 += bias[col0]; v1 += bias[col0 + 1]; }
                if (EPI & EPI_RELU) { v0 = fmaxf(v0, 0.f); v1 = fmaxf(v1, 0.f); }
                if (EPI & EPI_GELU) {
                    v0 = 0.5f * v0 * (1.f + erff(v0 * 0.70710678118654752f));
                    v1 = 0.5f * v1 * (1.f + erff(v1 * 0.70710678118654752f));
                }
                if (EPI & EPI_RES) {
                    v0 += res[gm * N + col0];
                    v1 += res[gm * N + col0 + 1];
                }
                *(float2*)(C + gm * N + col0) = make_float2(v0, v1);
            }
        }
    }
}

// transpose conv2 weights [D=256][C=256][3] -> [K=768 (j*256+c)][D=256]
__global__ void w2t_kernel(const float* __restrict__ w, float* __restrict__ o)
{
    int i = blockIdx.x * 256 + threadIdx.x;
    int d  = i & 255;
    int kk = i >> 8;
    int c  = kk & 255;
    int j  = kk >> 8;
    o[(long long)kk * 256 + d] = w[(long long)d * 768 + c * 3 + j];
}

// 64x64x16 fp32 tile version for small-M GEMMs (M=64). B is [K,N] only.
template<int EPI>
__global__ __launch_bounds__(256) void sgemm64(
    const float* __restrict__ A, const float* __restrict__ B,
    const float* __restrict__ bias, float* __restrict__ C,
    int M, int N, int K)
{
    __shared__ float As[16][64];
    __shared__ float Bs[16][64];
    int m0 = blockIdx.y * 64, n0 = blockIdx.x * 64;
    int t = threadIdx.x;
    int tx = t & 15, ty = t >> 4;
    float acc[4][4];
    #pragma unroll
    for (int i = 0; i < 4; i++)
        #pragma unroll
        for (int j = 0; j < 4; j++) acc[i][j] = 0.f;

    const int am = t >> 2, ak = (t & 3) * 4;
    const int bk = t >> 4, bn = (t & 15) * 4;

    for (int k0 = 0; k0 < K; k0 += 16) {
        float4 av = *(const float4*)(A + (long long)(m0 + am) * K + k0 + ak);
        As[ak + 0][am] = av.x; As[ak + 1][am] = av.y;
        As[ak + 2][am] = av.z; As[ak + 3][am] = av.w;
        *(float4*)&Bs[bk][bn] = *(const float4*)(B + (long long)(k0 + bk) * N + n0 + bn);
        __syncthreads();
        #pragma unroll
        for (int kk = 0; kk < 16; kk++) {
            float4 a4 = *(const float4*)&As[kk][ty * 4];
            float4 b4 = *(const float4*)&Bs[kk][tx * 4];
            float a[4] = {a4.x, a4.y, a4.z, a4.w};
            float b[4] = {b4.x, b4.y, b4.z, b4.w};
            #pragma unroll
            for (int i = 0; i < 4; i++)
                #pragma unroll
                for (int j = 0; j < 4; j++)
                    acc[i][j] += a[i] * b[j];
        }
        __syncthreads();
    }
    #pragma unroll
    for (int i = 0; i < 4; i++) {
        long long gm = m0 + ty * 4 + i;
        float vr[4];
        #pragma unroll
        for (int j = 0; j < 4; j++) {
            int gn = n0 + tx * 4 + j;
            float v = acc[i][j];
            if (EPI & EPI_BIAS) v += bias[gn];
            if (EPI & EPI_RELU) v = fmaxf(v, 0.f);
            vr[j] = v;
        }
        *(float4*)(C + gm * N + n0 + tx * 4) = make_float4(vr[0], vr[1], vr[2], vr[3]);
    }
}

// =====================================================================
// conv1: [B,L,16] -> relu(conv1d k=3 pad=1) -> [B,L,256]
// =====================================================================
__global__ __launch_bounds__(256) void conv1_kernel(
    const float* __restrict__ x, const float* __restrict__ w,
    const float* __restrict__ bias, float* __restrict__ out)
{
    int l = blockIdx.x, b = blockIdx.y, d = threadIdx.x;
    __shared__ float sx[3][16];
    if (d < 48) {
        int j = d / 16, c = d % 16;
        int ll = l + j - 1;
        sx[j][c] = (ll >= 0 && ll < LLEN) ? x[((long long)b * LLEN + ll) * CIN + c] : 0.f;
    }
    __syncthreads();
    float acc = bias[d];
    const float* wd = w + d * 48;
    #pragma unroll
    for (int c = 0; c < 16; c++)
        #pragma unroll
        for (int j = 0; j < 3; j++)
            acc += sx[j][c] * wd[c * 3 + j];
    out[((long long)b * LLEN + l) * DD + d] = fmaxf(acc, 0.f);
}

// =====================================================================
// LayerNorm over last dim = 256. 8 rows/block, 32 lanes/row, shuffle.
// =====================================================================
__global__ __launch_bounds__(256) void ln256_kernel(
    const float* __restrict__ in, const float* __restrict__ g,
    const float* __restrict__ bt, float* __restrict__ out,
    long long ostride, long long ooff)
{
    int t = threadIdx.x;
    int lane = t & 31, wr = t >> 5;
    long long r = (long long)blockIdx.x * 8 + wr;
    const float* ip = in + r * 256 + lane * 8;
    float4 v0 = *(const float4*)ip;
    float4 v1 = *(const float4*)(ip + 4);
    float x[8] = {v0.x, v0.y, v0.z, v0.w, v1.x, v1.y, v1.z, v1.w};
    float s = 0.f;
    #pragma unroll
    for (int j = 0; j < 8; j++) s += x[j];
    #pragma unroll
    for (int o = 16; o; o >>= 1) s += __shfl_xor_sync(0xFFFFFFFFu, s, o);
    float mean = s * (1.f / 256.f);
    float vs = 0.f;
    #pragma unroll
    for (int j = 0; j < 8; j++) { x[j] -= mean; vs += x[j] * x[j]; }
    #pragma unroll
    for (int o = 16; o; o >>= 1) vs += __shfl_xor_sync(0xFFFFFFFFu, vs, o);
    float inv = rsqrtf(vs * (1.f / 256.f) + 1e-5f);
    float4 g0 = *(const float4*)(g + lane * 8);
    float4 g1 = *(const float4*)(g + lane * 8 + 4);
    float4 b0 = *(const float4*)(bt + lane * 8);
    float4 b1 = *(const float4*)(bt + lane * 8 + 4);
    float gg[8] = {g0.x, g0.y, g0.z, g0.w, g1.x, g1.y, g1.z, g1.w};
    float bb[8] = {b0.x, b0.y, b0.z, b0.w, b1.x, b1.y, b1.z, b1.w};
    float o8[8];
    #pragma unroll
    for (int j = 0; j < 8; j++) o8[j] = x[j] * inv * gg[j] + bb[j];
    float* op = out + r * ostride + ooff + lane * 8;
    *(float4*)op       = make_float4(o8[0], o8[1], o8[2], o8[3]);
    *(float4*)(op + 4) = make_float4(o8[4], o8[5], o8[6], o8[7]);
}

// =====================================================================
// top-k(20) + softmax (ties -> lowest index, matches lax.top_k)
// reads rp[b][tau] (raw sums; mean = sum/256)
// =====================================================================
__global__ __launch_bounds__(256) void topk_kernel(
    const float* __restrict__ rp, int* __restrict__ del, float* __restrict__ wts)
{
    int b = blockIdx.x, t = threadIdx.x;
    __shared__ float sv[LLEN];
    __shared__ float rv[256];
    __shared__ int   ri[256];
    __shared__ float selv[TOPK];
    __shared__ int   seli[TOPK];
    for (int i = t; i < LLEN; i += 256)
        sv[i] = rp[(long long)b * LLEN + i] * (1.f / 256.f);
    __syncthreads();
    for (int iter = 0; iter < TOPK; iter++) {
        float bv = -INFINITY; int bi = 1 << 30;
        for (int i = t; i < LLEN; i += 256) {
            float v = sv[i];
            if (v > bv || (v == bv && i < bi)) { bv = v; bi = i; }
        }
        rv[t] = bv; ri[t] = bi; __syncthreads();
        for (int s = 128; s > 0; s >>= 1) {
            if (t < s) {
                if (rv[t + s] > rv[t] || (rv[t + s] == rv[t] && ri[t + s] < ri[t])) {
                    rv[t] = rv[t + s]; ri[t] = ri[t + s];
                }
            }
            __syncthreads();
        }
        if (t == 0) { selv[iter] = rv[0]; seli[iter] = ri[0]; sv[ri[0]] = -INFINITY; }
        __syncthreads();
    }
    if (t == 0) {
        float m = selv[0];
        float e[TOPK], ssum = 0.f;
        for (int k2 = 0; k2 < TOPK; k2++) { e[k2] = expf(selv[k2] - m); ssum += e[k2]; }
        float inv = 1.f / ssum;
        for (int k2 = 0; k2 < TOPK; k2++) {
            wts[b * TOPK + k2] = e[k2] * inv;
            del[b * TOPK + k2] = seli[k2];
        }
    }
}

// =====================================================================
// delayed aggregation: out[b,l,d] = sum_k w[k] * V[b,(l+delay[k])%L,d]
// 4 rows per block, float4 over d (64 lanes per row).
// =====================================================================
__global__ __launch_bounds__(256) void agg_kernel(
    const float* __restrict__ V, const int* __restrict__ del,
    const float* __restrict__ wts, float* __restrict__ out)
{
    int t = threadIdx.x;
    int b = blockIdx.y;
    int l = blockIdx.x * 4 + (t >> 6);
    int d4 = (t & 63) * 4;
    __shared__ int   sd[TOPK];
    __shared__ float sw[TOPK];
    if (t < TOPK) { sd[t] = del[b * TOPK + t]; sw[t] = wts[b * TOPK + t]; }
    __syncthreads();
    const float* vb = V + (long long)b * LLEN * DD;
    float a0 = 0.f, a1 = 0.f, a2 = 0.f, a3 = 0.f;
    #pragma unroll
    for (int k2 = 0; k2 < TOPK; k2++) {
        float w = sw[k2];
        float4 v = *(const float4*)(vb + (long long)((l + sd[k2]) & (LLEN - 1)) * DD + d4);
        a0 += w * v.x; a1 += w * v.y; a2 += w * v.z; a3 += w * v.w;
    }
    *(float4*)(out + ((long long)b * LLEN + l) * DD + d4) = make_float4(a0, a1, a2, a3);
}

// =====================================================================
// series decomposition: out = in - movavg25(in, replicate-pad)
// =====================================================================
__global__ __launch_bounds__(256) void decomp_kernel(
    const float* __restrict__ in, float* __restrict__ out)
{
    __shared__ float s[88][65];
    int b  = blockIdx.z;
    int c0 = blockIdx.y * 64;
    int l0 = blockIdx.x * 64;
    int t  = threadIdx.x;
    const float* base = in + (long long)b * LLEN * DD;
    for (int idx = t; idx < 88 * 64; idx += 256) {
        int r = idx >> 6, c = idx & 63;
        int ll = l0 - 12 + r;
        ll = max(0, min(LLEN - 1, ll));
        s[r][c] = base[(long long)ll * DD + c0 + c];
    }
    __syncthreads();
    int c = t & 63, lg = t >> 6;
    int lbase = lg * 16;
    float sum = 0.f;
    #pragma unroll
    for (int r = 0; r < MAW; r++) sum += s[lbase + r][c];
    float* ob = out + (long long)b * LLEN * DD;
    ob[(long long)(l0 + lbase) * DD + c0 + c] = s[lbase + 12][c] - sum * (1.f / MAW);
    #pragma unroll
    for (int i = 1; i < 16; i++) {
        sum += s[lbase + i + 24][c] - s[lbase + i - 1][c];
        ob[(long long)(l0 + lbase + i) * DD + c0 + c] = s[lbase + i + 12][c] - sum * (1.f / MAW);
    }
}

__global__ void pool_copy_kernel(const float* __restrict__ enc, float* __restrict__ fin, int off)
{
    int b = blockIdx.x, d = threadIdx.x;
    fin[b * (NLAY * DD + HSZ) + off + d] = enc[((long long)b * LLEN + (LLEN - 1)) * DD + d];
}

__global__ __launch_bounds__(256) void rp2_kernel(
    const float* __restrict__ o2, const float* __restrict__ w,
    const float* __restrict__ bias, float* __restrict__ out)
{
    int b = blockIdx.x, t = threadIdx.x;
    __shared__ float red[256];
    red[t] = o2[b * 256 + t] * w[t];
    __syncthreads();
    for (int s = 128; s > 0; s >>= 1) { if (t < s) red[t] += red[t + s]; __syncthreads(); }
    if (t == 0) out[b] = red[0] + bias[0];
}

// =====================================================================
// launch
// =====================================================================
extern "C" void kernel_launch(void* const* d_in, const int* in_sizes, int n_in,
                              void* d_out, int out_size)
{
    (void)in_sizes; (void)n_in; (void)out_size;
    const float* x_enc     = (const float*)d_in[0];
    const float* conv1_w   = (const float*)d_in[1];
    const float* conv1_b   = (const float*)d_in[2];
    const float* conv2_w   = (const float*)d_in[3];
    const float* conv2_b   = (const float*)d_in[4];
    const float* cnn_ln_g  = (const float*)d_in[5];
    const float* cnn_ln_b  = (const float*)d_in[6];
    const float* proj_w    = (const float*)d_in[7];
    const float* proj_b    = (const float*)d_in[8];
    const float* proj_ln_g = (const float*)d_in[9];
    const float* proj_ln_b = (const float*)d_in[10];
    const float* Wq        = (const float*)d_in[11];
    const float* bq        = (const float*)d_in[12];
    const float* Wk        = (const float*)d_in[13];
    const float* bk        = (const float*)d_in[14];
    const float* Wv        = (const float*)d_in[15];
    const float* bv        = (const float*)d_in[16];
    const float* Wo        = (const float*)d_in[17];
    const float* bo        = (const float*)d_in[18];
    const float* Wff1      = (const float*)d_in[19];
    const float* Wff2      = (const float*)d_in[20];
    const float* rp1_w     = (const float*)d_in[21];
    const float* rp1_b     = (const float*)d_in[22];
    const float* rp_ln_g   = (const float*)d_in[23];
    const float* rp_ln_b   = (const float*)d_in[24];
    const float* rp2_w     = (const float*)d_in[25];
    const float* rp2_b     = (const float*)d_in[26];
    float* out = (float*)d_out;

    float *p_h1, *p_enc, *p_q, *p_k, *p_v, *p_ac, *p_xs, *p_xd, *p_big, *p_rp;
    float *p_emb, *p_final, *p_o1, *p_o2, *p_w, *p_w2t;
    int* p_del;
    cudaGetSymbolAddress((void**)&p_h1,  g_h1);
    cudaGetSymbolAddress((void**)&p_enc, g_enc);
    cudaGetSymbolAddress((void**)&p_q,   g_q);
    cudaGetSymbolAddress((void**)&p_k,   g_k);
    cudaGetSymbolAddress((void**)&p_v,   g_v);
    cudaGetSymbolAddress((void**)&p_ac,  g_ac);
    cudaGetSymbolAddress((void**)&p_xs,  g_xs);
    cudaGetSymbolAddress((void**)&p_xd,  g_xd);
    cudaGetSymbolAddress((void**)&p_big, g_big);
    cudaGetSymbolAddress((void**)&p_rp,  g_rp);
    cudaGetSymbolAddress((void**)&p_del, g_del);
    cudaGetSymbolAddress((void**)&p_w,   g_w);
    cudaGetSymbolAddress((void**)&p_emb, g_emb);
    cudaGetSymbolAddress((void**)&p_final, g_final);
    cudaGetSymbolAddress((void**)&p_o1,  g_o1);
    cudaGetSymbolAddress((void**)&p_o2,  g_o2);
    cudaGetSymbolAddress((void**)&p_w2t, g_w2t);

    const int MBL = BB * LLEN;  // 65536
    const long long SLD = (long long)LLEN * DD;

    // opt-in to 84.5KB dynamic smem for every tgemm instantiation (idempotent)
    cudaFuncSetAttribute(tgemm128<1, false, EPI_BIAS | EPI_RELU>, cudaFuncAttributeMaxDynamicSharedMemorySize, TG_DYN_BYTES);
    cudaFuncSetAttribute(tgemm128<0, false, EPI_BIAS>,            cudaFuncAttributeMaxDynamicSharedMemorySize, TG_DYN_BYTES);
    cudaFuncSetAttribute(tgemm128<0, true,  EPI_GRAM>,            cudaFuncAttributeMaxDynamicSharedMemorySize, TG_DYN_BYTES);
    cudaFuncSetAttribute(tgemm128<0, false, EPI_BIAS | EPI_RES>,  cudaFuncAttributeMaxDynamicSharedMemorySize, TG_DYN_BYTES);
    cudaFuncSetAttribute(tgemm128<0, true,  EPI_GELU>,            cudaFuncAttributeMaxDynamicSharedMemorySize, TG_DYN_BYTES);
    cudaFuncSetAttribute(tgemm128<0, true,  EPI_RES>,             cudaFuncAttributeMaxDynamicSharedMemorySize, TG_DYN_BYTES);

    // CNN frontend
    conv1_kernel<<<dim3(LLEN, BB), 256>>>(x_enc, conv1_w, conv1_b, p_h1);
    w2t_kernel<<<768, 256>>>(conv2_w, p_w2t);
    tgemm128<1, false, EPI_BIAS | EPI_RELU><<<dim3(2, 8, BB), 256, TG_DYN_BYTES>>>(
        p_h1, p_w2t, conv2_b, nullptr, p_xs, LLEN, DD, 768, SLD, 0, SLD);
    ln256_kernel<<<MBL / 8, 256>>>(p_xs, cnn_ln_g, cnn_ln_b, p_enc, 256, 0);

    for (int i = 0; i < NLAY; i++) {
        const float* Wq_i  = Wq + (long long)i * DD * DD;
        const float* Wk_i  = Wk + (long long)i * DD * DD;
        const float* Wv_i  = Wv + (long long)i * DD * DD;
        const float* Wo_i  = Wo + (long long)i * DD * DD;
        const float* Wf1_i = Wff1 + (long long)i * DFF * DD;
        const float* Wf2_i = Wff2 + (long long)i * DD * DFF;
        const float* bq_i = bq + i * DD;
        const float* bk_i = bk + i * DD;
        const float* bv_i = bv + i * DD;
        const float* bo_i = bo + i * DD;

        // QKV projections (tf32 TC)
        tgemm128<0, false, EPI_BIAS><<<dim3(2, 512, 1), 256, TG_DYN_BYTES>>>(p_enc, Wq_i, bq_i, nullptr, p_q, MBL, DD, DD, 0, 0, 0);
        tgemm128<0, false, EPI_BIAS><<<dim3(2, 512, 1), 256, TG_DYN_BYTES>>>(p_enc, Wk_i, bk_i, nullptr, p_k, MBL, DD, DD, 0, 0, 0);
        tgemm128<0, false, EPI_BIAS><<<dim3(2, 512, 1), 256, TG_DYN_BYTES>>>(p_enc, Wv_i, bv_i, nullptr, p_v, MBL, DD, DD, 0, 0, 0);

        // fused Gram + wrapped-diagonal reduction -> rp[b][tau]
        cudaMemsetAsync(p_rp, 0, (size_t)BB * LLEN * sizeof(float));
        tgemm128<0, true, EPI_GRAM><<<dim3(8, 8, BB), 256, TG_DYN_BYTES>>>(p_q, p_k, nullptr, nullptr, p_rp,
                                                                           LLEN, LLEN, DD, SLD, SLD, LLEN);
        topk_kernel<<<BB, 256>>>(p_rp, p_del, p_w);
        agg_kernel<<<dim3(LLEN / 4, BB), 256>>>(p_v, p_del, p_w, p_ac);

        // x = enc + (ac @ Wo + bo)
        tgemm128<0, false, EPI_BIAS | EPI_RES><<<dim3(2, 512, 1), 256, TG_DYN_BYTES>>>(p_ac, Wo_i, bo_i, p_enc, p_xs, MBL, DD, DD, 0, 0, 0);
        decomp_kernel<<<dim3(16, 4, BB), 256>>>(p_xs, p_xd);

        // FFN (tf32 TC)
        tgemm128<0, true, EPI_GELU><<<dim3(8, 512, 1), 256, TG_DYN_BYTES>>>(p_xd, Wf1_i, nullptr, nullptr, p_big, MBL, DFF, DD, 0, 0, 0);
        tgemm128<0, true, EPI_RES><<<dim3(2, 512, 1), 256, TG_DYN_BYTES>>>(p_big, Wf2_i, nullptr, p_xd, p_xs, MBL, DD, DFF, 0, 0, 0);
        decomp_kernel<<<dim3(16, 4, BB), 256>>>(p_xs, p_enc);

        pool_copy_kernel<<<BB, 256>>>(p_enc, p_final, i * DD);
    }

    // input embed head
    sgemm64<EPI_BIAS | EPI_RELU><<<dim3(4, 1), 256>>>(x_enc, proj_w, proj_b, p_emb, BB, HSZ, LLEN * CIN);
    ln256_kernel<<<BB / 8, 256>>>(p_emb, proj_ln_g, proj_ln_b, p_final, NLAY * DD + HSZ, NLAY * DD);

    // regression head
    sgemm64<EPI_BIAS | EPI_RELU><<<dim3(4, 1), 256>>>(p_final, rp1_w, rp1_b, p_o1, BB, HSZ, NLAY * DD + HSZ);
    ln256_kernel<<<BB / 8, 256>>>(p_o1, rp_ln_g, rp_ln_b, p_o2, 256, 0);
    rp2_kernel<<<BB, 256>>>(p_o2, rp2_w, rp2_b, out);
}

// round 11
// speedup vs baseline: 1.0963x; 1.0963x over previous
#include <cuda_runtime.h>
#include <cuda_bf16.h>
#include <math.h>

// ---------------- static problem config ----------------
#define BB   64
#define LLEN 1024
#define CIN  16
#define DD   256
#define HH   8
#define DFF  1024
#define HSZ  256
#define NLAY 2
#define TOPK 20
#define MAW  25   // moving average window

// ---------------- device scratch (no allocs allowed) ----------------
__device__ __align__(16) float g_h1 [BB*LLEN*DD];            // conv1 out
__device__ __align__(16) float g_enc[BB*LLEN*DD];            // encoder state
__device__ __align__(16) float g_q  [BB*LLEN*DD];
__device__ __align__(16) float g_k  [BB*LLEN*DD];
__device__ __align__(16) float g_v  [BB*LLEN*DD];
__device__ __align__(16) float g_ac [BB*LLEN*DD];            // autocorr agg out
__device__ __align__(16) float g_xs [BB*LLEN*DD];            // x (pre-decomp) / conv2 out
__device__ __align__(16) float g_xd [BB*LLEN*DD];            // x after decomp
__device__ __align__(16) float g_big[BB*LLEN*DFF];           // FFN hidden
__device__ __align__(16) float g_rp [BB*LLEN];               // correlation sums per tau
__device__ int   g_del[BB*TOPK];
__device__ float g_w  [BB*TOPK];
__device__ __align__(16) float g_emb[BB*HSZ];
__device__ __align__(16) float g_final[BB*(NLAY*DD+HSZ)];    // [64][768]
__device__ __align__(16) float g_o1[BB*HSZ];
__device__ __align__(16) float g_o2[BB*HSZ];
__device__ __align__(16) float g_w2t[768*256];               // conv2 weights as [K=768][N=256]

// ---------------- epilogue flags ----------------
#define EPI_BIAS 1
#define EPI_RELU 2
#define EPI_GELU 4
#define EPI_RES  8
#define EPI_GRAM 16   // no C tile write; reduce wrapped diagonals into C (=rp+b*1024)

__device__ __forceinline__ unsigned f2tf(float f) {
    unsigned u;
    asm("cvt.rna.tf32.f32 %0, %1;" : "=r"(u) : "f"(f));
    return u;
}

__device__ __forceinline__ void mma_tf32(float* c, const unsigned* a, const unsigned* b) {
    asm volatile(
        "mma.sync.aligned.m16n8k8.row.col.f32.tf32.tf32.f32 "
        "{%0,%1,%2,%3}, {%4,%5,%6,%7}, {%8,%9}, {%0,%1,%2,%3};\n"
        : "+f"(c[0]), "+f"(c[1]), "+f"(c[2]), "+f"(c[3])
        : "r"(a[0]), "r"(a[1]), "r"(a[2]), "r"(a[3]), "r"(b[0]), "r"(b[1]));
}

// 16B cp.async with zero-fill predicate (src_size = 0 -> all zeros)
__device__ __forceinline__ void cp16(unsigned smem_addr, const void* gptr, bool pred) {
    int sz = pred ? 16 : 0;
    asm volatile("cp.async.cg.shared.global [%0], [%1], 16, %2;\n"
                 :: "r"(smem_addr), "l"(gptr), "r"(sz));
}
__device__ __forceinline__ void cp_commit() {
    asm volatile("cp.async.commit_group;\n");
}
__device__ __forceinline__ void cp_wait0() {
    asm volatile("cp.async.wait_group 0;\n");
}

// =====================================================================
// tf32 tensor-core GEMM, 128x128x16 CTA tile, 128 threads (4 warps),
// warp tile 64x64 (warps 2 x 2), mma m16n8k8.
// Large warp tile halves per-MAC smem fragment traffic vs 8x(64x32):
// each A element now feeds 2 warps (was 4). 2-stage cp.async pipeline
// (best-measured structure from R8). Tiles in smem as RAW fp32; tf32
// rounding (cvt.rna) at fragment load -- math identical.
//
// smem layouts (conflict-free fragment reads + 16B cp.async chunks):
//   A (and TB-true B): [row][k], row stride 20 floats
//   TB-false B:        [k][n],   k stride 136 floats
//
// AMODE: 0 = normal A [M,K]; 1 = conv2 shifted-A (A is h1[L,256], K=768,
//        k-chunk j in {0,1,2} reads row l+j-1 with zero padding).
// TB: false -> B[K,N] row-major; true -> B[N,K] row-major.
// Batched via gridDim.z with element strides sA,sB,sC.
// EPI_GRAM: reduce tile into wrapped-diagonal sums:
//           C[(m-n)&1023] += acc  (C is rp + b*1024, pre-zeroed).
// =====================================================================
#define ASTRIDE 20
#define ASTAGE  (128 * ASTRIDE)   // 2560 floats per stage
#define BSTAGE  2720              // max(128*20, 16*136) floats per stage

template<int AMODE, bool TB, int EPI>
__global__ __launch_bounds__(128) void tgemm128(
    const float* __restrict__ A, const float* __restrict__ B,
    const float* __restrict__ bias, const float* __restrict__ res,
    float* __restrict__ C, int M, int N, int K,
    long long sA, long long sB, long long sC)
{
    __shared__ float Asm[2 * ASTAGE];
    __shared__ float Bsm[2 * BSTAGE];
    __shared__ float sdiag[256];
    long long bz = blockIdx.z;
    A += bz * sA;  B += bz * sB;  C += bz * sC;
    if (EPI & EPI_RES) res += bz * sC;

    int m0 = blockIdx.y * 128, n0 = blockIdx.x * 128;
    int t = threadIdx.x;
    int wid = t >> 5, lane = t & 31;
    int g = lane >> 2, t4 = lane & 3;
    int wm = (wid & 1) * 64;
    int wn = (wid >> 1) * 64;

    unsigned sA_u = (unsigned)__cvta_generic_to_shared(Asm);
    unsigned sB_u = (unsigned)__cvta_generic_to_shared(Bsm);

    float acc[4][8][4];
    #pragma unroll
    for (int mi = 0; mi < 4; mi++)
        #pragma unroll
        for (int ni = 0; ni < 8; ni++)
            #pragma unroll
            for (int r = 0; r < 4; r++) acc[mi][ni][r] = 0.f;

    // copy assignment: A tile = 512 16B-chunks, B tile = 512 chunks,
    // 128 threads -> 4 A-chunks + 4 B-chunks per thread.
#define ISSUE_COPY(ST, K0)                                                     \
    {                                                                          \
        _Pragma("unroll")                                                      \
        for (int j = 0; j < 4; j++) {                                          \
            int c   = t + j * 128;                                             \
            int row = c >> 2;                                                  \
            int kc  = (c & 3) * 4;                                             \
            unsigned as = sA_u + ((ST) * ASTAGE + row * ASTRIDE + kc) * 4;     \
            if (AMODE == 0) {                                                  \
                cp16(as, A + (long long)(m0 + row) * K + (K0) + kc, true);     \
            } else {                                                           \
                int kk = (K0) + kc;                                            \
                int sft = kk >> 8;                                             \
                int cc  = kk & 255;                                            \
                int ll  = m0 + row + sft - 1;                                  \
                bool ok = (ll >= 0 && ll < LLEN);                              \
                const float* gp = ok ? (A + (long long)ll * 256 + cc) : A;     \
                cp16(as, gp, ok);                                              \
            }                                                                  \
        }                                                                      \
        _Pragma("unroll")                                                      \
        for (int j = 0; j < 4; j++) {                                          \
            int c = t + j * 128;                                               \
            if (TB) {                                                          \
                int n   = c >> 2;                                              \
                int kc  = (c & 3) * 4;                                         \
                unsigned bs = sB_u + ((ST) * BSTAGE + n * ASTRIDE + kc) * 4;   \
                cp16(bs, B + (long long)(n0 + n) * K + (K0) + kc, true);       \
            } else {                                                           \
                int bk = c >> 5;                                               \
                int bn = (c & 31) * 4;                                         \
                unsigned bs = sB_u + ((ST) * BSTAGE + bk * 136 + bn) * 4;      \
                cp16(bs, B + (long long)((K0) + bk) * N + n0 + bn, true);      \
            }                                                                  \
        }                                                                      \
    }

    const int KT = K / 16;
    ISSUE_COPY(0, 0);
    cp_commit();

    for (int it = 0; it < KT; it++) {
        cp_wait0();
        __syncthreads();
        if (it + 1 < KT) ISSUE_COPY((it + 1) & 1, (it + 1) * 16);
        cp_commit();

        const float* As  = Asm + (it & 1) * ASTAGE;
        const float* Bsr = Bsm + (it & 1) * BSTAGE;

        #pragma unroll
        for (int ks = 0; ks < 2; ks++) {
            int k0f = ks * 8 + t4;
            unsigned afr[4][4], bfr[8][2];
            #pragma unroll
            for (int mi = 0; mi < 4; mi++) {
                int mr = wm + mi * 16 + g;
                afr[mi][0] = f2tf(As[mr * ASTRIDE + k0f]);
                afr[mi][1] = f2tf(As[(mr + 8) * ASTRIDE + k0f]);
                afr[mi][2] = f2tf(As[mr * ASTRIDE + k0f + 4]);
                afr[mi][3] = f2tf(As[(mr + 8) * ASTRIDE + k0f + 4]);
            }
            #pragma unroll
            for (int ni = 0; ni < 8; ni++) {
                int nc = wn + ni * 8 + g;
                if (TB) {
                    bfr[ni][0] = f2tf(Bsr[nc * ASTRIDE + k0f]);
                    bfr[ni][1] = f2tf(Bsr[nc * ASTRIDE + k0f + 4]);
                } else {
                    bfr[ni][0] = f2tf(Bsr[k0f * 136 + nc]);
                    bfr[ni][1] = f2tf(Bsr[(k0f + 4) * 136 + nc]);
                }
            }
            #pragma unroll
            for (int mi = 0; mi < 4; mi++)
                #pragma unroll
                for (int ni = 0; ni < 8; ni++)
                    mma_tf32(acc[mi][ni], afr[mi], bfr[ni]);
        }
        __syncthreads();
    }
#undef ISSUE_COPY

    if (EPI & EPI_GRAM) {
        // wrapped-diagonal reduction of this 128x128 tile into tau bins.
        sdiag[t] = 0.f;
        sdiag[t + 128] = 0.f;
        __syncthreads();
        #pragma unroll
        for (int mi = 0; mi < 4; mi++) {
            #pragma unroll
            for (int ni = 0; ni < 8; ni++) {
                int li0 = wm + mi * 16 + g;
                int lj0 = wn + ni * 8 + t4 * 2;
                #pragma unroll
                for (int half = 0; half < 2; half++) {
                    int li = li0 + half * 8;
                    atomicAdd(&sdiag[li - lj0 + 127],     acc[mi][ni][half * 2 + 0]);
                    atomicAdd(&sdiag[li - (lj0+1) + 127], acc[mi][ni][half * 2 + 1]);
                }
            }
        }
        __syncthreads();
        for (int i = t; i < 255; i += 128) {
            int tau = (m0 - n0 - 127 + i) & (LLEN - 1);
            atomicAdd(&C[tau], sdiag[i]);
        }
        return;
    }

    #pragma unroll
    for (int mi = 0; mi < 4; mi++) {
        #pragma unroll
        for (int ni = 0; ni < 8; ni++) {
            long long row0 = m0 + wm + mi * 16 + g;
            int col0 = n0 + wn + ni * 8 + t4 * 2;
            #pragma unroll
            for (int half = 0; half < 2; half++) {
                long long gm = row0 + half * 8;
                float v0 = acc[mi][ni][half * 2 + 0];
                float v1 = acc[mi][ni][half * 2 + 1];
                if (EPI & EPI_BIAS) { v0 += bias[col0]; v1 += bias[col0 + 1]; }
                if (EPI & EPI_RELU) { v0 = fmaxf(v0, 0.f); v1 = fmaxf(v1, 0.f); }
                if (EPI & EPI_GELU) {
                    v0 = 0.5f * v0 * (1.f + erff(v0 * 0.70710678118654752f));
                    v1 = 0.5f * v1 * (1.f + erff(v1 * 0.70710678118654752f));
                }
                if (EPI & EPI_RES) {
                    v0 += res[gm * N + col0];
                    v1 += res[gm * N + col0 + 1];
                }
                *(float2*)(C + gm * N + col0) = make_float2(v0, v1);
            }
        }
    }
}

// transpose conv2 weights [D=256][C=256][3] -> [K=768 (j*256+c)][D=256]
__global__ void w2t_kernel(const float* __restrict__ w, float* __restrict__ o)
{
    int i = blockIdx.x * 256 + threadIdx.x;
    int d  = i & 255;
    int kk = i >> 8;
    int c  = kk & 255;
    int j  = kk >> 8;
    o[(long long)kk * 256 + d] = w[(long long)d * 768 + c * 3 + j];
}

// 64x64x16 fp32 tile version for small-M GEMMs (M=64). B is [K,N] only.
template<int EPI>
__global__ __launch_bounds__(256) void sgemm64(
    const float* __restrict__ A, const float* __restrict__ B,
    const float* __restrict__ bias, float* __restrict__ C,
    int M, int N, int K)
{
    __shared__ float As[16][64];
    __shared__ float Bs[16][64];
    int m0 = blockIdx.y * 64, n0 = blockIdx.x * 64;
    int t = threadIdx.x;
    int tx = t & 15, ty = t >> 4;
    float acc[4][4];
    #pragma unroll
    for (int i = 0; i < 4; i++)
        #pragma unroll
        for (int j = 0; j < 4; j++) acc[i][j] = 0.f;

    const int am = t >> 2, ak = (t & 3) * 4;
    const int bk = t >> 4, bn = (t & 15) * 4;

    for (int k0 = 0; k0 < K; k0 += 16) {
        float4 av = *(const float4*)(A + (long long)(m0 + am) * K + k0 + ak);
        As[ak + 0][am] = av.x; As[ak + 1][am] = av.y;
        As[ak + 2][am] = av.z; As[ak + 3][am] = av.w;
        *(float4*)&Bs[bk][bn] = *(const float4*)(B + (long long)(k0 + bk) * N + n0 + bn);
        __syncthreads();
        #pragma unroll
        for (int kk = 0; kk < 16; kk++) {
            float4 a4 = *(const float4*)&As[kk][ty * 4];
            float4 b4 = *(const float4*)&Bs[kk][tx * 4];
            float a[4] = {a4.x, a4.y, a4.z, a4.w};
            float b[4] = {b4.x, b4.y, b4.z, b4.w};
            #pragma unroll
            for (int i = 0; i < 4; i++)
                #pragma unroll
                for (int j = 0; j < 4; j++)
                    acc[i][j] += a[i] * b[j];
        }
        __syncthreads();
    }
    #pragma unroll
    for (int i = 0; i < 4; i++) {
        long long gm = m0 + ty * 4 + i;
        float vr[4];
        #pragma unroll
        for (int j = 0; j < 4; j++) {
            int gn = n0 + tx * 4 + j;
            float v = acc[i][j];
            if (EPI & EPI_BIAS) v += bias[gn];
            if (EPI & EPI_RELU) v = fmaxf(v, 0.f);
            vr[j] = v;
        }
        *(float4*)(C + gm * N + n0 + tx * 4) = make_float4(vr[0], vr[1], vr[2], vr[3]);
    }
}

// =====================================================================
// conv1: [B,L,16] -> relu(conv1d k=3 pad=1) -> [B,L,256]
// =====================================================================
__global__ __launch_bounds__(256) void conv1_kernel(
    const float* __restrict__ x, const float* __restrict__ w,
    const float* __restrict__ bias, float* __restrict__ out)
{
    int l = blockIdx.x, b = blockIdx.y, d = threadIdx.x;
    __shared__ float sx[3][16];
    if (d < 48) {
        int j = d / 16, c = d % 16;
        int ll = l + j - 1;
        sx[j][c] = (ll >= 0 && ll < LLEN) ? x[((long long)b * LLEN + ll) * CIN + c] : 0.f;
    }
    __syncthreads();
    float acc = bias[d];
    const float* wd = w + d * 48;
    #pragma unroll
    for (int c = 0; c < 16; c++)
        #pragma unroll
        for (int j = 0; j < 3; j++)
            acc += sx[j][c] * wd[c * 3 + j];
    out[((long long)b * LLEN + l) * DD + d] = fmaxf(acc, 0.f);
}

// =====================================================================
// LayerNorm over last dim = 256. 8 rows/block, 32 lanes/row, shuffle.
// =====================================================================
__global__ __launch_bounds__(256) void ln256_kernel(
    const float* __restrict__ in, const float* __restrict__ g,
    const float* __restrict__ bt, float* __restrict__ out,
    long long ostride, long long ooff)
{
    int t = threadIdx.x;
    int lane = t & 31, wr = t >> 5;
    long long r = (long long)blockIdx.x * 8 + wr;
    const float* ip = in + r * 256 + lane * 8;
    float4 v0 = *(const float4*)ip;
    float4 v1 = *(const float4*)(ip + 4);
    float x[8] = {v0.x, v0.y, v0.z, v0.w, v1.x, v1.y, v1.z, v1.w};
    float s = 0.f;
    #pragma unroll
    for (int j = 0; j < 8; j++) s += x[j];
    #pragma unroll
    for (int o = 16; o; o >>= 1) s += __shfl_xor_sync(0xFFFFFFFFu, s, o);
    float mean = s * (1.f / 256.f);
    float vs = 0.f;
    #pragma unroll
    for (int j = 0; j < 8; j++) { x[j] -= mean; vs += x[j] * x[j]; }
    #pragma unroll
    for (int o = 16; o; o >>= 1) vs += __shfl_xor_sync(0xFFFFFFFFu, vs, o);
    float inv = rsqrtf(vs * (1.f / 256.f) + 1e-5f);
    float4 g0 = *(const float4*)(g + lane * 8);
    float4 g1 = *(const float4*)(g + lane * 8 + 4);
    float4 b0 = *(const float4*)(bt + lane * 8);
    float4 b1 = *(const float4*)(bt + lane * 8 + 4);
    float gg[8] = {g0.x, g0.y, g0.z, g0.w, g1.x, g1.y, g1.z, g1.w};
    float bb[8] = {b0.x, b0.y, b0.z, b0.w, b1.x, b1.y, b1.z, b1.w};
    float o8[8];
    #pragma unroll
    for (int j = 0; j < 8; j++) o8[j] = x[j] * inv * gg[j] + bb[j];
    float* op = out + r * ostride + ooff + lane * 8;
    *(float4*)op       = make_float4(o8[0], o8[1], o8[2], o8[3]);
    *(float4*)(op + 4) = make_float4(o8[4], o8[5], o8[6], o8[7]);
}

// =====================================================================
// top-k(20) + softmax (ties -> lowest index, matches lax.top_k)
// reads rp[b][tau] (raw sums; mean = sum/256)
// =====================================================================
__global__ __launch_bounds__(256) void topk_kernel(
    const float* __restrict__ rp, int* __restrict__ del, float* __restrict__ wts)
{
    int b = blockIdx.x, t = threadIdx.x;
    __shared__ float sv[LLEN];
    __shared__ float rv[256];
    __shared__ int   ri[256];
    __shared__ float selv[TOPK];
    __shared__ int   seli[TOPK];
    for (int i = t; i < LLEN; i += 256)
        sv[i] = rp[(long long)b * LLEN + i] * (1.f / 256.f);
    __syncthreads();
    for (int iter = 0; iter < TOPK; iter++) {
        float bv = -INFINITY; int bi = 1 << 30;
        for (int i = t; i < LLEN; i += 256) {
            float v = sv[i];
            if (v > bv || (v == bv && i < bi)) { bv = v; bi = i; }
        }
        rv[t] = bv; ri[t] = bi; __syncthreads();
        for (int s = 128; s > 0; s >>= 1) {
            if (t < s) {
                if (rv[t + s] > rv[t] || (rv[t + s] == rv[t] && ri[t + s] < ri[t])) {
                    rv[t] = rv[t + s]; ri[t] = ri[t + s];
                }
            }
            __syncthreads();
        }
        if (t == 0) { selv[iter] = rv[0]; seli[iter] = ri[0]; sv[ri[0]] = -INFINITY; }
        __syncthreads();
    }
    if (t == 0) {
        float m = selv[0];
        float e[TOPK], ssum = 0.f;
        for (int k2 = 0; k2 < TOPK; k2++) { e[k2] = expf(selv[k2] - m); ssum += e[k2]; }
        float inv = 1.f / ssum;
        for (int k2 = 0; k2 < TOPK; k2++) {
            wts[b * TOPK + k2] = e[k2] * inv;
            del[b * TOPK + k2] = seli[k2];
        }
    }
}

// =====================================================================
// delayed aggregation: out[b,l,d] = sum_k w[k] * V[b,(l+delay[k])%L,d]
// 4 rows per block, float4 over d (64 lanes per row).
// =====================================================================
__global__ __launch_bounds__(256) void agg_kernel(
    const float* __restrict__ V, const int* __restrict__ del,
    const float* __restrict__ wts, float* __restrict__ out)
{
    int t = threadIdx.x;
    int b = blockIdx.y;
    int l = blockIdx.x * 4 + (t >> 6);
    int d4 = (t & 63) * 4;
    __shared__ int   sd[TOPK];
    __shared__ float sw[TOPK];
    if (t < TOPK) { sd[t] = del[b * TOPK + t]; sw[t] = wts[b * TOPK + t]; }
    __syncthreads();
    const float* vb = V + (long long)b * LLEN * DD;
    float a0 = 0.f, a1 = 0.f, a2 = 0.f, a3 = 0.f;
    #pragma unroll
    for (int k2 = 0; k2 < TOPK; k2++) {
        float w = sw[k2];
        float4 v = *(const float4*)(vb + (long long)((l + sd[k2]) & (LLEN - 1)) * DD + d4);
        a0 += w * v.x; a1 += w * v.y; a2 += w * v.z; a3 += w * v.w;
    }
    *(float4*)(out + ((long long)b * LLEN + l) * DD + d4) = make_float4(a0, a1, a2, a3);
}

// =====================================================================
// series decomposition: out = in - movavg25(in, replicate-pad)
// =====================================================================
__global__ __launch_bounds__(256) void decomp_kernel(
    const float* __restrict__ in, float* __restrict__ out)
{
    __shared__ float s[88][65];
    int b  = blockIdx.z;
    int c0 = blockIdx.y * 64;
    int l0 = blockIdx.x * 64;
    int t  = threadIdx.x;
    const float* base = in + (long long)b * LLEN * DD;
    for (int idx = t; idx < 88 * 64; idx += 256) {
        int r = idx >> 6, c = idx & 63;
        int ll = l0 - 12 + r;
        ll = max(0, min(LLEN - 1, ll));
        s[r][c] = base[(long long)ll * DD + c0 + c];
    }
    __syncthreads();
    int c = t & 63, lg = t >> 6;
    int lbase = lg * 16;
    float sum = 0.f;
    #pragma unroll
    for (int r = 0; r < MAW; r++) sum += s[lbase + r][c];
    float* ob = out + (long long)b * LLEN * DD;
    ob[(long long)(l0 + lbase) * DD + c0 + c] = s[lbase + 12][c] - sum * (1.f / MAW);
    #pragma unroll
    for (int i = 1; i < 16; i++) {
        sum += s[lbase + i + 24][c] - s[lbase + i - 1][c];
        ob[(long long)(l0 + lbase + i) * DD + c0 + c] = s[lbase + i + 12][c] - sum * (1.f / MAW);
    }
}

__global__ void pool_copy_kernel(const float* __restrict__ enc, float* __restrict__ fin, int off)
{
    int b = blockIdx.x, d = threadIdx.x;
    fin[b * (NLAY * DD + HSZ) + off + d] = enc[((long long)b * LLEN + (LLEN - 1)) * DD + d];
}

__global__ __launch_bounds__(256) void rp2_kernel(
    const float* __restrict__ o2, const float* __restrict__ w,
    const float* __restrict__ bias, float* __restrict__ out)
{
    int b = blockIdx.x, t = threadIdx.x;
    __shared__ float red[256];
    red[t] = o2[b * 256 + t] * w[t];
    __syncthreads();
    for (int s = 128; s > 0; s >>= 1) { if (t < s) red[t] += red[t + s]; __syncthreads(); }
    if (t == 0) out[b] = red[0] + bias[0];
}

// =====================================================================
// launch
// =====================================================================
extern "C" void kernel_launch(void* const* d_in, const int* in_sizes, int n_in,
                              void* d_out, int out_size)
{
    (void)in_sizes; (void)n_in; (void)out_size;
    const float* x_enc     = (const float*)d_in[0];
    const float* conv1_w   = (const float*)d_in[1];
    const float* conv1_b   = (const float*)d_in[2];
    const float* conv2_w   = (const float*)d_in[3];
    const float* conv2_b   = (const float*)d_in[4];
    const float* cnn_ln_g  = (const float*)d_in[5];
    const float* cnn_ln_b  = (const float*)d_in[6];
    const float* proj_w    = (const float*)d_in[7];
    const float* proj_b    = (const float*)d_in[8];
    const float* proj_ln_g = (const float*)d_in[9];
    const float* proj_ln_b = (const float*)d_in[10];
    const float* Wq        = (const float*)d_in[11];
    const float* bq        = (const float*)d_in[12];
    const float* Wk        = (const float*)d_in[13];
    const float* bk        = (const float*)d_in[14];
    const float* Wv        = (const float*)d_in[15];
    const float* bv        = (const float*)d_in[16];
    const float* Wo        = (const float*)d_in[17];
    const float* bo        = (const float*)d_in[18];
    const float* Wff1      = (const float*)d_in[19];
    const float* Wff2      = (const float*)d_in[20];
    const float* rp1_w     = (const float*)d_in[21];
    const float* rp1_b     = (const float*)d_in[22];
    const float* rp_ln_g   = (const float*)d_in[23];
    const float* rp_ln_b   = (const float*)d_in[24];
    const float* rp2_w     = (const float*)d_in[25];
    const float* rp2_b     = (const float*)d_in[26];
    float* out = (float*)d_out;

    float *p_h1, *p_enc, *p_q, *p_k, *p_v, *p_ac, *p_xs, *p_xd, *p_big, *p_rp;
    float *p_emb, *p_final, *p_o1, *p_o2, *p_w, *p_w2t;
    int* p_del;
    cudaGetSymbolAddress((void**)&p_h1,  g_h1);
    cudaGetSymbolAddress((void**)&p_enc, g_enc);
    cudaGetSymbolAddress((void**)&p_q,   g_q);
    cudaGetSymbolAddress((void**)&p_k,   g_k);
    cudaGetSymbolAddress((void**)&p_v,   g_v);
    cudaGetSymbolAddress((void**)&p_ac,  g_ac);
    cudaGetSymbolAddress((void**)&p_xs,  g_xs);
    cudaGetSymbolAddress((void**)&p_xd,  g_xd);
    cudaGetSymbolAddress((void**)&p_big, g_big);
    cudaGetSymbolAddress((void**)&p_rp,  g_rp);
    cudaGetSymbolAddress((void**)&p_del, g_del);
    cudaGetSymbolAddress((void**)&p_w,   g_w);
    cudaGetSymbolAddress((void**)&p_emb, g_emb);
    cudaGetSymbolAddress((void**)&p_final, g_final);
    cudaGetSymbolAddress((void**)&p_o1,  g_o1);
    cudaGetSymbolAddress((void**)&p_o2,  g_o2);
    cudaGetSymbolAddress((void**)&p_w2t, g_w2t);

    const int MBL = BB * LLEN;  // 65536
    const long long SLD = (long long)LLEN * DD;

    // input embed head launched FIRST (only depends on x_enc) so the ncu
    // fixed profiling slot lands on a tgemm128 launch below.
    sgemm64<EPI_BIAS | EPI_RELU><<<dim3(4, 1), 256>>>(x_enc, proj_w, proj_b, p_emb, BB, HSZ, LLEN * CIN);

    // CNN frontend
    w2t_kernel<<<768, 256>>>(conv2_w, p_w2t);
    conv1_kernel<<<dim3(LLEN, BB), 256>>>(x_enc, conv1_w, conv1_b, p_h1);
    tgemm128<1, false, EPI_BIAS | EPI_RELU><<<dim3(2, 8, BB), 128>>>(
        p_h1, p_w2t, conv2_b, nullptr, p_xs, LLEN, DD, 768, SLD, 0, SLD);
    ln256_kernel<<<MBL / 8, 256>>>(p_xs, cnn_ln_g, cnn_ln_b, p_enc, 256, 0);

    for (int i = 0; i < NLAY; i++) {
        const float* Wq_i  = Wq + (long long)i * DD * DD;
        const float* Wk_i  = Wk + (long long)i * DD * DD;
        const float* Wv_i  = Wv + (long long)i * DD * DD;
        const float* Wo_i  = Wo + (long long)i * DD * DD;
        const float* Wf1_i = Wff1 + (long long)i * DFF * DD;
        const float* Wf2_i = Wff2 + (long long)i * DD * DFF;
        const float* bq_i = bq + i * DD;
        const float* bk_i = bk + i * DD;
        const float* bv_i = bv + i * DD;
        const float* bo_i = bo + i * DD;

        // QKV projections (tf32 TC)
        tgemm128<0, false, EPI_BIAS><<<dim3(2, 512, 1), 128>>>(p_enc, Wq_i, bq_i, nullptr, p_q, MBL, DD, DD, 0, 0, 0);
        tgemm128<0, false, EPI_BIAS><<<dim3(2, 512, 1), 128>>>(p_enc, Wk_i, bk_i, nullptr, p_k, MBL, DD, DD, 0, 0, 0);
        tgemm128<0, false, EPI_BIAS><<<dim3(2, 512, 1), 128>>>(p_enc, Wv_i, bv_i, nullptr, p_v, MBL, DD, DD, 0, 0, 0);

        // fused Gram + wrapped-diagonal reduction -> rp[b][tau]
        cudaMemsetAsync(p_rp, 0, (size_t)BB * LLEN * sizeof(float));
        tgemm128<0, true, EPI_GRAM><<<dim3(8, 8, BB), 128>>>(p_q, p_k, nullptr, nullptr, p_rp,
                                                             LLEN, LLEN, DD, SLD, SLD, LLEN);
        topk_kernel<<<BB, 256>>>(p_rp, p_del, p_w);
        agg_kernel<<<dim3(LLEN / 4, BB), 256>>>(p_v, p_del, p_w, p_ac);

        // x = enc + (ac @ Wo + bo)
        tgemm128<0, false, EPI_BIAS | EPI_RES><<<dim3(2, 512, 1), 128>>>(p_ac, Wo_i, bo_i, p_enc, p_xs, MBL, DD, DD, 0, 0, 0);
        decomp_kernel<<<dim3(16, 4, BB), 256>>>(p_xs, p_xd);

        // FFN (tf32 TC)
        tgemm128<0, true, EPI_GELU><<<dim3(8, 512, 1), 128>>>(p_xd, Wf1_i, nullptr, nullptr, p_big, MBL, DFF, DD, 0, 0, 0);
        tgemm128<0, true, EPI_RES><<<dim3(2, 512, 1), 128>>>(p_big, Wf2_i, nullptr, p_xd, p_xs, MBL, DD, DFF, 0, 0, 0);
        decomp_kernel<<<dim3(16, 4, BB), 256>>>(p_xs, p_enc);

        pool_copy_kernel<<<BB, 256>>>(p_enc, p_final, i * DD);
    }

    // input embed LN into final feature buffer
    ln256_kernel<<<BB / 8, 256>>>(p_emb, proj_ln_g, proj_ln_b, p_final, NLAY * DD + HSZ, NLAY * DD);

    // regression head
    sgemm64<EPI_BIAS | EPI_RELU><<<dim3(4, 1), 256>>>(p_final, rp1_w, rp1_b, p_o1, BB, HSZ, NLAY * DD + HSZ);
    ln256_kernel<<<BB / 8, 256>>>(p_o1, rp_ln_g, rp_ln_b, p_o2, 256, 0);
    rp2_kernel<<<BB, 256>>>(p_o2, rp2_w, rp2_b, out);
}

// round 14
// speedup vs baseline: 1.3656x; 1.2457x over previous
#include <cuda_runtime.h>
#include <cuda_bf16.h>
#include <math.h>

// ---------------- static problem config ----------------
#define BB   64
#define LLEN 1024
#define CIN  16
#define DD   256
#define HH   8
#define DFF  1024
#define HSZ  256
#define NLAY 2
#define TOPK 20
#define MAW  25   // moving average window

// ---------------- device scratch (no allocs allowed) ----------------
__device__ __align__(16) float g_h1 [BB*LLEN*DD];            // conv1 out
__device__ __align__(16) float g_enc[BB*LLEN*DD];            // encoder state
__device__ __align__(16) float g_qkv[BB*LLEN*768];           // fused q|k|v
__device__ __align__(16) float g_ac [BB*LLEN*DD];            // autocorr agg out
__device__ __align__(16) float g_xs [BB*LLEN*DD];            // x (pre-decomp) / conv2 out
__device__ __align__(16) float g_xd [BB*LLEN*DD];            // x after decomp
__device__ __align__(16) float g_big[BB*LLEN*DFF];           // FFN hidden
__device__ __align__(16) float g_rp [BB*LLEN];               // correlation sums per tau
__device__ int   g_del[BB*TOPK];
__device__ float g_w  [BB*TOPK];
__device__ __align__(16) float g_emb[BB*HSZ];
__device__ __align__(16) float g_final[BB*(NLAY*DD+HSZ)];    // [64][768]
__device__ __align__(16) float g_o1[BB*HSZ];
__device__ __align__(16) float g_o2[BB*HSZ];
__device__ __align__(16) float g_w2t[768*256];               // conv2 weights as [K=768][N=256]
__device__ __align__(16) float g_wqkv[NLAY*256*768];         // packed QKV weights [K=256][N=768]
__device__ __align__(16) float g_bqkv[NLAY*768];

// ---------------- epilogue flags ----------------
#define EPI_BIAS 1
#define EPI_RELU 2
#define EPI_GELU 4
#define EPI_RES  8
#define EPI_GRAM 16   // no C tile write; reduce wrapped diagonals into C (=rp+b*1024)

__device__ __forceinline__ unsigned f2tf(float f) {
    unsigned u;
    asm("cvt.rna.tf32.f32 %0, %1;" : "=r"(u) : "f"(f));
    return u;
}

__device__ __forceinline__ void mma_tf32(float* c, const unsigned* a, const unsigned* b) {
    asm volatile(
        "mma.sync.aligned.m16n8k8.row.col.f32.tf32.tf32.f32 "
        "{%0,%1,%2,%3}, {%4,%5,%6,%7}, {%8,%9}, {%0,%1,%2,%3};\n"
        : "+f"(c[0]), "+f"(c[1]), "+f"(c[2]), "+f"(c[3])
        : "r"(a[0]), "r"(a[1]), "r"(a[2]), "r"(a[3]), "r"(b[0]), "r"(b[1]));
}

// 16B cp.async with zero-fill predicate (src_size = 0 -> all zeros)
__device__ __forceinline__ void cp16(unsigned smem_addr, const void* gptr, bool pred) {
    int sz = pred ? 16 : 0;
    asm volatile("cp.async.cg.shared.global [%0], [%1], 16, %2;\n"
                 :: "r"(smem_addr), "l"(gptr), "r"(sz));
}
__device__ __forceinline__ void cp_commit() {
    asm volatile("cp.async.commit_group;\n");
}
__device__ __forceinline__ void cp_wait0() {
    asm volatile("cp.async.wait_group 0;\n");
}

// =====================================================================
// tf32 tensor-core GEMM, 128x128x32 CTA tile, 128 threads (4 warps),
// warp tile 64x64 (warps 2 x 2), mma m16n8k8.
// K-tile=32 halves sync/wait overhead vs K=16. 2-stage cp.async
// pipeline (best-measured structure). Tiles in smem as RAW fp32; tf32
// rounding (cvt.rna) at fragment load -- math identical.
//
// lda = A row stride (elements); ldb = B row stride.
//   TB=false: B[K][N] rows of ldb (=N for our uses)
//   TB=true : B[N][K] rows of ldb
//
// smem layouts (conflict-free fragment reads + 16B cp.async chunks):
//   A (and TB-true B): [row][k], row stride 36 floats
//   TB-false B:        [k][n],   k stride 136 floats
//
// AMODE: 0 = normal A; 1 = conv2 shifted-A (A is h1[L,256], K=768,
//        k-chunk j in {0,1,2} reads row l+j-1 with zero padding).
// Batched via gridDim.z with element strides sA,sB,sC.
// EPI_GRAM: reduce tile into wrapped-diagonal sums:
//           C[(m-n)&1023] += acc  (C is rp + b*1024, pre-zeroed).
// =====================================================================
#define ASTRIDE 36
#define ASTG  (128 * ASTRIDE)     // 4608 floats per stage
#define BSTG  4608                // max(128*36, 32*136)
#define TG_DYN_BYTES (2 * (ASTG + BSTG) * 4)   // 73728

template<int AMODE, bool TB, int EPI>
__global__ __launch_bounds__(128) void tgemm128(
    const float* __restrict__ A, const float* __restrict__ B,
    const float* __restrict__ bias, const float* __restrict__ res,
    float* __restrict__ C, int M, int N, int K, int lda, int ldb,
    long long sA, long long sB, long long sC)
{
    extern __shared__ float dynsm[];
    float* Asm = dynsm;               // 2 * ASTG
    float* Bsm = dynsm + 2 * ASTG;    // 2 * BSTG
    __shared__ float sdiag[256];
    long long bz = blockIdx.z;
    A += bz * sA;  B += bz * sB;  C += bz * sC;
    if (EPI & EPI_RES) res += bz * sC;

    int m0 = blockIdx.y * 128, n0 = blockIdx.x * 128;
    int t = threadIdx.x;
    int wid = t >> 5, lane = t & 31;
    int g = lane >> 2, t4 = lane & 3;
    int wm = (wid & 1) * 64;
    int wn = (wid >> 1) * 64;

    unsigned sA_u = (unsigned)__cvta_generic_to_shared(Asm);
    unsigned sB_u = (unsigned)__cvta_generic_to_shared(Bsm);

    float acc[4][8][4];
    #pragma unroll
    for (int mi = 0; mi < 4; mi++)
        #pragma unroll
        for (int ni = 0; ni < 8; ni++)
            #pragma unroll
            for (int r = 0; r < 4; r++) acc[mi][ni][r] = 0.f;

    // copy assignment: A tile = 1024 16B-chunks, B tile = 1024 chunks,
    // 128 threads -> 8 A-chunks + 8 B-chunks per thread.
#define ISSUE_COPY(ST, K0)                                                     \
    {                                                                          \
        _Pragma("unroll")                                                      \
        for (int j = 0; j < 8; j++) {                                          \
            int c   = t + j * 128;                                             \
            int row = c >> 3;                                                  \
            int kc  = (c & 7) * 4;                                             \
            unsigned as = sA_u + ((ST) * ASTG + row * ASTRIDE + kc) * 4;       \
            if (AMODE == 0) {                                                  \
                cp16(as, A + (long long)(m0 + row) * lda + (K0) + kc, true);   \
            } else {                                                           \
                int kk = (K0) + kc;                                            \
                int sft = kk >> 8;                                             \
                int cc  = kk & 255;                                            \
                int ll  = m0 + row + sft - 1;                                  \
                bool ok = (ll >= 0 && ll < LLEN);                              \
                const float* gp = ok ? (A + (long long)ll * 256 + cc) : A;     \
                cp16(as, gp, ok);                                              \
            }                                                                  \
        }                                                                      \
        _Pragma("unroll")                                                      \
        for (int j = 0; j < 8; j++) {                                          \
            int c = t + j * 128;                                               \
            if (TB) {                                                          \
                int n   = c >> 3;                                              \
                int kc  = (c & 7) * 4;                                         \
                unsigned bs = sB_u + ((ST) * BSTG + n * ASTRIDE + kc) * 4;     \
                cp16(bs, B + (long long)(n0 + n) * ldb + (K0) + kc, true);     \
            } else {                                                           \
                int bk = c >> 5;                                               \
                int bn = (c & 31) * 4;                                         \
                unsigned bs = sB_u + ((ST) * BSTG + bk * 136 + bn) * 4;        \
                cp16(bs, B + (long long)((K0) + bk) * ldb + n0 + bn, true);    \
            }                                                                  \
        }                                                                      \
    }

    const int KT = K / 32;
    ISSUE_COPY(0, 0);
    cp_commit();

    for (int it = 0; it < KT; it++) {
        cp_wait0();
        __syncthreads();
        if (it + 1 < KT) ISSUE_COPY((it + 1) & 1, (it + 1) * 32);
        cp_commit();

        const float* As  = Asm + (it & 1) * ASTG;
        const float* Bsr = Bsm + (it & 1) * BSTG;

        #pragma unroll
        for (int ks = 0; ks < 4; ks++) {
            int k0f = ks * 8 + t4;
            unsigned afr[4][4], bfr[8][2];
            #pragma unroll
            for (int mi = 0; mi < 4; mi++) {
                int mr = wm + mi * 16 + g;
                afr[mi][0] = f2tf(As[mr * ASTRIDE + k0f]);
                afr[mi][1] = f2tf(As[(mr + 8) * ASTRIDE + k0f]);
                afr[mi][2] = f2tf(As[mr * ASTRIDE + k0f + 4]);
                afr[mi][3] = f2tf(As[(mr + 8) * ASTRIDE + k0f + 4]);
            }
            #pragma unroll
            for (int ni = 0; ni < 8; ni++) {
                int nc = wn + ni * 8 + g;
                if (TB) {
                    bfr[ni][0] = f2tf(Bsr[nc * ASTRIDE + k0f]);
                    bfr[ni][1] = f2tf(Bsr[nc * ASTRIDE + k0f + 4]);
                } else {
                    bfr[ni][0] = f2tf(Bsr[k0f * 136 + nc]);
                    bfr[ni][1] = f2tf(Bsr[(k0f + 4) * 136 + nc]);
                }
            }
            #pragma unroll
            for (int mi = 0; mi < 4; mi++)
                #pragma unroll
                for (int ni = 0; ni < 8; ni++)
                    mma_tf32(acc[mi][ni], afr[mi], bfr[ni]);
        }
        __syncthreads();
    }
#undef ISSUE_COPY

    if (EPI & EPI_GRAM) {
        // wrapped-diagonal reduction of this 128x128 tile into tau bins.
        sdiag[t] = 0.f;
        sdiag[t + 128] = 0.f;
        __syncthreads();
        #pragma unroll
        for (int mi = 0; mi < 4; mi++) {
            #pragma unroll
            for (int ni = 0; ni < 8; ni++) {
                int li0 = wm + mi * 16 + g;
                int lj0 = wn + ni * 8 + t4 * 2;
                #pragma unroll
                for (int half = 0; half < 2; half++) {
                    int li = li0 + half * 8;
                    atomicAdd(&sdiag[li - lj0 + 127],     acc[mi][ni][half * 2 + 0]);
                    atomicAdd(&sdiag[li - (lj0+1) + 127], acc[mi][ni][half * 2 + 1]);
                }
            }
        }
        __syncthreads();
        for (int i = t; i < 255; i += 128) {
            int tau = (m0 - n0 - 127 + i) & (LLEN - 1);
            atomicAdd(&C[tau], sdiag[i]);
        }
        return;
    }

    #pragma unroll
    for (int mi = 0; mi < 4; mi++) {
        #pragma unroll
        for (int ni = 0; ni < 8; ni++) {
            long long row0 = m0 + wm + mi * 16 + g;
            int col0 = n0 + wn + ni * 8 + t4 * 2;
            #pragma unroll
            for (int half = 0; half < 2; half++) {
                long long gm = row0 + half * 8;
                float v0 = acc[mi][ni][half * 2 + 0];
                float v1 = acc[mi][ni][half * 2 + 1];
                if (EPI & EPI_BIAS) { v0 += bias[col0]; v1 += bias[col0 + 1]; }
                if (EPI & EPI_RELU) { v0 = fmaxf(v0, 0.f); v1 = fmaxf(v1, 0.f); }
                if (EPI & EPI_GELU) {
                    v0 = 0.5f * v0 * (1.f + erff(v0 * 0.70710678118654752f));
                    v1 = 0.5f * v1 * (1.f + erff(v1 * 0.70710678118654752f));
                }
                if (EPI & EPI_RES) {
                    v0 += res[gm * N + col0];
                    v1 += res[gm * N + col0 + 1];
                }
                *(float2*)(C + gm * N + col0) = make_float2(v0, v1);
            }
        }
    }
}

// transpose conv2 weights [D=256][C=256][3] -> [K=768 (j*256+c)][D=256]
__global__ void w2t_kernel(const float* __restrict__ w, float* __restrict__ o)
{
    int i = blockIdx.x * 256 + threadIdx.x;
    int d  = i & 255;
    int kk = i >> 8;
    int c  = kk & 255;
    int j  = kk >> 8;
    o[(long long)kk * 256 + d] = w[(long long)d * 768 + c * 3 + j];
}

// pack QKV weights: [lay][K=256][N=768] where N segment 0/1/2 = Wq/Wk/Wv
__global__ void packqkv_kernel(
    const float* __restrict__ Wq, const float* __restrict__ Wk,
    const float* __restrict__ Wv, const float* __restrict__ bq,
    const float* __restrict__ bk, const float* __restrict__ bv,
    float* __restrict__ wout, float* __restrict__ bout)
{
    long long i = (long long)blockIdx.x * 256 + threadIdx.x;   // NLAY*256*768
    int lay = (int)(i / 196608);
    int j   = (int)(i - (long long)lay * 196608);
    int k   = j / 768;
    int n   = j - k * 768;
    int seg = n >> 8, col = n & 255;
    const float* W = (seg == 0) ? Wq : (seg == 1) ? Wk : Wv;
    wout[i] = W[(long long)lay * 65536 + k * 256 + col];
    if (j < 768) {
        const float* bb = (seg == 0) ? bq : (seg == 1) ? bk : bv;
        bout[lay * 768 + j] = bb[lay * 256 + col];
    }
}

// 64x64x16 fp32 tile version for small-M GEMMs (M=64). B is [K,N] only.
template<int EPI>
__global__ __launch_bounds__(256) void sgemm64(
    const float* __restrict__ A, const float* __restrict__ B,
    const float* __restrict__ bias, float* __restrict__ C,
    int M, int N, int K)
{
    __shared__ float As[16][64];
    __shared__ float Bs[16][64];
    int m0 = blockIdx.y * 64, n0 = blockIdx.x * 64;
    int t = threadIdx.x;
    int tx = t & 15, ty = t >> 4;
    float acc[4][4];
    #pragma unroll
    for (int i = 0; i < 4; i++)
        #pragma unroll
        for (int j = 0; j < 4; j++) acc[i][j] = 0.f;

    const int am = t >> 2, ak = (t & 3) * 4;
    const int bk = t >> 4, bn = (t & 15) * 4;

    for (int k0 = 0; k0 < K; k0 += 16) {
        float4 av = *(const float4*)(A + (long long)(m0 + am) * K + k0 + ak);
        As[ak + 0][am] = av.x; As[ak + 1][am] = av.y;
        As[ak + 2][am] = av.z; As[ak + 3][am] = av.w;
        *(float4*)&Bs[bk][bn] = *(const float4*)(B + (long long)(k0 + bk) * N + n0 + bn);
        __syncthreads();
        #pragma unroll
        for (int kk = 0; kk < 16; kk++) {
            float4 a4 = *(const float4*)&As[kk][ty * 4];
            float4 b4 = *(const float4*)&Bs[kk][tx * 4];
            float a[4] = {a4.x, a4.y, a4.z, a4.w};
            float b[4] = {b4.x, b4.y, b4.z, b4.w};
            #pragma unroll
            for (int i = 0; i < 4; i++)
                #pragma unroll
                for (int j = 0; j < 4; j++)
                    acc[i][j] += a[i] * b[j];
        }
        __syncthreads();
    }
    #pragma unroll
    for (int i = 0; i < 4; i++) {
        long long gm = m0 + ty * 4 + i;
        float vr[4];
        #pragma unroll
        for (int j = 0; j < 4; j++) {
            int gn = n0 + tx * 4 + j;
            float v = acc[i][j];
            if (EPI & EPI_BIAS) v += bias[gn];
            if (EPI & EPI_RELU) v = fmaxf(v, 0.f);
            vr[j] = v;
        }
        *(float4*)(C + gm * N + n0 + tx * 4) = make_float4(vr[0], vr[1], vr[2], vr[3]);
    }
}

// =====================================================================
// conv1: [B,L,16] -> relu(conv1d k=3 pad=1) -> [B,L,256]
// 16 l-rows per block; weights register-resident.
// =====================================================================
__global__ __launch_bounds__(256) void conv1_kernel(
    const float* __restrict__ x, const float* __restrict__ w,
    const float* __restrict__ bias, float* __restrict__ out)
{
    int b = blockIdx.y, l0 = blockIdx.x * 16, d = threadIdx.x;
    __shared__ float sx[18][16];
    for (int idx = d; idx < 18 * 16; idx += 256) {
        int r = idx >> 4, c = idx & 15;
        int ll = l0 - 1 + r;
        sx[r][c] = (ll >= 0 && ll < LLEN) ? x[((long long)b * LLEN + ll) * CIN + c] : 0.f;
    }
    __syncthreads();
    float wreg[48];
    #pragma unroll
    for (int i = 0; i < 48; i++) wreg[i] = w[d * 48 + i];
    float bd = bias[d];
    #pragma unroll 4
    for (int i = 0; i < 16; i++) {
        float acc = bd;
        #pragma unroll
        for (int c = 0; c < 16; c++)
            #pragma unroll
            for (int j = 0; j < 3; j++)
                acc += sx[i + j][c] * wreg[c * 3 + j];
        out[((long long)b * LLEN + l0 + i) * DD + d] = fmaxf(acc, 0.f);
    }
}

// =====================================================================
// LayerNorm over last dim = 256. 8 rows/block, 32 lanes/row, shuffle.
// =====================================================================
__global__ __launch_bounds__(256) void ln256_kernel(
    const float* __restrict__ in, const float* __restrict__ g,
    const float* __restrict__ bt, float* __restrict__ out,
    long long ostride, long long ooff)
{
    int t = threadIdx.x;
    int lane = t & 31, wr = t >> 5;
    long long r = (long long)blockIdx.x * 8 + wr;
    const float* ip = in + r * 256 + lane * 8;
    float4 v0 = *(const float4*)ip;
    float4 v1 = *(const float4*)(ip + 4);
    float x[8] = {v0.x, v0.y, v0.z, v0.w, v1.x, v1.y, v1.z, v1.w};
    float s = 0.f;
    #pragma unroll
    for (int j = 0; j < 8; j++) s += x[j];
    #pragma unroll
    for (int o = 16; o; o >>= 1) s += __shfl_xor_sync(0xFFFFFFFFu, s, o);
    float mean = s * (1.f / 256.f);
    float vs = 0.f;
    #pragma unroll
    for (int j = 0; j < 8; j++) { x[j] -= mean; vs += x[j] * x[j]; }
    #pragma unroll
    for (int o = 16; o; o >>= 1) vs += __shfl_xor_sync(0xFFFFFFFFu, vs, o);
    float inv = rsqrtf(vs * (1.f / 256.f) + 1e-5f);
    float4 g0 = *(const float4*)(g + lane * 8);
    float4 g1 = *(const float4*)(g + lane * 8 + 4);
    float4 b0 = *(const float4*)(bt + lane * 8);
    float4 b1 = *(const float4*)(bt + lane * 8 + 4);
    float gg[8] = {g0.x, g0.y, g0.z, g0.w, g1.x, g1.y, g1.z, g1.w};
    float bb[8] = {b0.x, b0.y, b0.z, b0.w, b1.x, b1.y, b1.z, b1.w};
    float o8[8];
    #pragma unroll
    for (int j = 0; j < 8; j++) o8[j] = x[j] * inv * gg[j] + bb[j];
    float* op = out + r * ostride + ooff + lane * 8;
    *(float4*)op       = make_float4(o8[0], o8[1], o8[2], o8[3]);
    *(float4*)(op + 4) = make_float4(o8[4], o8[5], o8[6], o8[7]);
}

// =====================================================================
// top-k(20) + softmax (ties -> lowest index, matches lax.top_k)
// =====================================================================
__global__ __launch_bounds__(256) void topk_kernel(
    const float* __restrict__ rp, int* __restrict__ del, float* __restrict__ wts)
{
    int b = blockIdx.x, t = threadIdx.x;
    __shared__ float sv[LLEN];
    __shared__ float rv[256];
    __shared__ int   ri[256];
    __shared__ float selv[TOPK];
    __shared__ int   seli[TOPK];
    for (int i = t; i < LLEN; i += 256)
        sv[i] = rp[(long long)b * LLEN + i] * (1.f / 256.f);
    __syncthreads();
    for (int iter = 0; iter < TOPK; iter++) {
        float bv = -INFINITY; int bi = 1 << 30;
        for (int i = t; i < LLEN; i += 256) {
            float v = sv[i];
            if (v > bv || (v == bv && i < bi)) { bv = v; bi = i; }
        }
        rv[t] = bv; ri[t] = bi; __syncthreads();
        for (int s = 128; s > 0; s >>= 1) {
            if (t < s) {
                if (rv[t + s] > rv[t] || (rv[t + s] == rv[t] && ri[t + s] < ri[t])) {
                    rv[t] = rv[t + s]; ri[t] = ri[t + s];
                }
            }
            __syncthreads();
        }
        if (t == 0) { selv[iter] = rv[0]; seli[iter] = ri[0]; sv[ri[0]] = -INFINITY; }
        __syncthreads();
    }
    if (t == 0) {
        float m = selv[0];
        float e[TOPK], ssum = 0.f;
        for (int k2 = 0; k2 < TOPK; k2++) { e[k2] = expf(selv[k2] - m); ssum += e[k2]; }
        float inv = 1.f / ssum;
        for (int k2 = 0; k2 < TOPK; k2++) {
            wts[b * TOPK + k2] = e[k2] * inv;
            del[b * TOPK + k2] = seli[k2];
        }
    }
}

// =====================================================================
// delayed aggregation: out[b,l,d] = sum_k w[k] * V[b,(l+delay[k])%L,d]
// V = qkv + 512, row stride 768. 4 rows/block, float4 over d.
// =====================================================================
__global__ __launch_bounds__(256) void agg_kernel(
    const float* __restrict__ QKV, const int* __restrict__ del,
    const float* __restrict__ wts, float* __restrict__ out)
{
    int t = threadIdx.x;
    int b = blockIdx.y;
    int l = blockIdx.x * 4 + (t >> 6);
    int d4 = (t & 63) * 4;
    __shared__ int   sd[TOPK];
    __shared__ float sw[TOPK];
    if (t < TOPK) { sd[t] = del[b * TOPK + t]; sw[t] = wts[b * TOPK + t]; }
    __syncthreads();
    const float* vb = QKV + (long long)b * LLEN * 768 + 512;
    float a0 = 0.f, a1 = 0.f, a2 = 0.f, a3 = 0.f;
    #pragma unroll
    for (int k2 = 0; k2 < TOPK; k2++) {
        float w = sw[k2];
        float4 v = *(const float4*)(vb + (long long)((l + sd[k2]) & (LLEN - 1)) * 768 + d4);
        a0 += w * v.x; a1 += w * v.y; a2 += w * v.z; a3 += w * v.w;
    }
    *(float4*)(out + ((long long)b * LLEN + l) * DD + d4) = make_float4(a0, a1, a2, a3);
}

// =====================================================================
// series decomposition: out = in - movavg25(in, replicate-pad)
// =====================================================================
__global__ __launch_bounds__(256) void decomp_kernel(
    const float* __restrict__ in, float* __restrict__ out)
{
    __shared__ float s[88][65];
    int b  = blockIdx.z;
    int c0 = blockIdx.y * 64;
    int l0 = blockIdx.x * 64;
    int t  = threadIdx.x;
    const float* base = in + (long long)b * LLEN * DD;
    for (int idx = t; idx < 88 * 64; idx += 256) {
        int r = idx >> 6, c = idx & 63;
        int ll = l0 - 12 + r;
        ll = max(0, min(LLEN - 1, ll));
        s[r][c] = base[(long long)ll * DD + c0 + c];
    }
    __syncthreads();
    int c = t & 63, lg = t >> 6;
    int lbase = lg * 16;
    float sum = 0.f;
    #pragma unroll
    for (int r = 0; r < MAW; r++) sum += s[lbase + r][c];
    float* ob = out + (long long)b * LLEN * DD;
    ob[(long long)(l0 + lbase) * DD + c0 + c] = s[lbase + 12][c] - sum * (1.f / MAW);
    #pragma unroll
    for (int i = 1; i < 16; i++) {
        sum += s[lbase + i + 24][c] - s[lbase + i - 1][c];
        ob[(long long)(l0 + lbase + i) * DD + c0 + c] = s[lbase + i + 12][c] - sum * (1.f / MAW);
    }
}

__global__ void pool_copy_kernel(const float* __restrict__ enc, float* __restrict__ fin, int off)
{
    int b = blockIdx.x, d = threadIdx.x;
    fin[b * (NLAY * DD + HSZ) + off + d] = enc[((long long)b * LLEN + (LLEN - 1)) * DD + d];
}

__global__ __launch_bounds__(256) void rp2_kernel(
    const float* __restrict__ o2, const float* __restrict__ w,
    const float* __restrict__ bias, float* __restrict__ out)
{
    int b = blockIdx.x, t = threadIdx.x;
    __shared__ float red[256];
    red[t] = o2[b * 256 + t] * w[t];
    __syncthreads();
    for (int s = 128; s > 0; s >>= 1) { if (t < s) red[t] += red[t + s]; __syncthreads(); }
    if (t == 0) out[b] = red[0] + bias[0];
}

// =====================================================================
// launch
// =====================================================================
extern "C" void kernel_launch(void* const* d_in, const int* in_sizes, int n_in,
                              void* d_out, int out_size)
{
    (void)in_sizes; (void)n_in; (void)out_size;
    const float* x_enc     = (const float*)d_in[0];
    const float* conv1_w   = (const float*)d_in[1];
    const float* conv1_b   = (const float*)d_in[2];
    const float* conv2_w   = (const float*)d_in[3];
    const float* conv2_b   = (const float*)d_in[4];
    const float* cnn_ln_g  = (const float*)d_in[5];
    const float* cnn_ln_b  = (const float*)d_in[6];
    const float* proj_w    = (const float*)d_in[7];
    const float* proj_b    = (const float*)d_in[8];
    const float* proj_ln_g = (const float*)d_in[9];
    const float* proj_ln_b = (const float*)d_in[10];
    const float* Wq        = (const float*)d_in[11];
    const float* bq        = (const float*)d_in[12];
    const float* Wk        = (const float*)d_in[13];
    const float* bk        = (const float*)d_in[14];
    const float* Wv        = (const float*)d_in[15];
    const float* bv        = (const float*)d_in[16];
    const float* Wo        = (const float*)d_in[17];
    const float* bo        = (const float*)d_in[18];
    const float* Wff1      = (const float*)d_in[19];
    const float* Wff2      = (const float*)d_in[20];
    const float* rp1_w     = (const float*)d_in[21];
    const float* rp1_b     = (const float*)d_in[22];
    const float* rp_ln_g   = (const float*)d_in[23];
    const float* rp_ln_b   = (const float*)d_in[24];
    const float* rp2_w     = (const float*)d_in[25];
    const float* rp2_b     = (const float*)d_in[26];
    float* out = (float*)d_out;

    float *p_h1, *p_enc, *p_qkv, *p_ac, *p_xs, *p_xd, *p_big, *p_rp;
    float *p_emb, *p_final, *p_o1, *p_o2, *p_w, *p_w2t, *p_wqkv, *p_bqkv;
    int* p_del;
    cudaGetSymbolAddress((void**)&p_h1,  g_h1);
    cudaGetSymbolAddress((void**)&p_enc, g_enc);
    cudaGetSymbolAddress((void**)&p_qkv, g_qkv);
    cudaGetSymbolAddress((void**)&p_ac,  g_ac);
    cudaGetSymbolAddress((void**)&p_xs,  g_xs);
    cudaGetSymbolAddress((void**)&p_xd,  g_xd);
    cudaGetSymbolAddress((void**)&p_big, g_big);
    cudaGetSymbolAddress((void**)&p_rp,  g_rp);
    cudaGetSymbolAddress((void**)&p_del, g_del);
    cudaGetSymbolAddress((void**)&p_w,   g_w);
    cudaGetSymbolAddress((void**)&p_emb, g_emb);
    cudaGetSymbolAddress((void**)&p_final, g_final);
    cudaGetSymbolAddress((void**)&p_o1,  g_o1);
    cudaGetSymbolAddress((void**)&p_o2,  g_o2);
    cudaGetSymbolAddress((void**)&p_w2t, g_w2t);
    cudaGetSymbolAddress((void**)&p_wqkv, g_wqkv);
    cudaGetSymbolAddress((void**)&p_bqkv, g_bqkv);

    const int MBL = BB * LLEN;  // 65536
    const long long SLD = (long long)LLEN * DD;
    const long long SLQ = (long long)LLEN * 768;

    // opt-in to 72KB dynamic smem for every tgemm instantiation
    cudaFuncSetAttribute(tgemm128<1, false, EPI_BIAS | EPI_RELU>, cudaFuncAttributeMaxDynamicSharedMemorySize, TG_DYN_BYTES);
    cudaFuncSetAttribute(tgemm128<0, false, EPI_BIAS>,            cudaFuncAttributeMaxDynamicSharedMemorySize, TG_DYN_BYTES);
    cudaFuncSetAttribute(tgemm128<0, true,  EPI_GRAM>,            cudaFuncAttributeMaxDynamicSharedMemorySize, TG_DYN_BYTES);
    cudaFuncSetAttribute(tgemm128<0, false, EPI_BIAS | EPI_RES>,  cudaFuncAttributeMaxDynamicSharedMemorySize, TG_DYN_BYTES);
    cudaFuncSetAttribute(tgemm128<0, true,  EPI_GELU>,            cudaFuncAttributeMaxDynamicSharedMemorySize, TG_DYN_BYTES);
    cudaFuncSetAttribute(tgemm128<0, true,  EPI_RES>,             cudaFuncAttributeMaxDynamicSharedMemorySize, TG_DYN_BYTES);

    // prep + frontend (ordering also aims the ncu capture slot at a tgemm)
    w2t_kernel<<<768, 256>>>(conv2_w, p_w2t);
    packqkv_kernel<<<NLAY * 768, 256>>>(Wq, Wk, Wv, bq, bk, bv, p_wqkv, p_bqkv);
    conv1_kernel<<<dim3(LLEN / 16, BB), 256>>>(x_enc, conv1_w, conv1_b, p_h1);
    tgemm128<1, false, EPI_BIAS | EPI_RELU><<<dim3(2, 8, BB), 128, TG_DYN_BYTES>>>(
        p_h1, p_w2t, conv2_b, nullptr, p_xs, LLEN, DD, 768, 256, 256, SLD, 0, SLD);
    sgemm64<EPI_BIAS | EPI_RELU><<<dim3(4, 1), 256>>>(x_enc, proj_w, proj_b, p_emb, BB, HSZ, LLEN * CIN);
    ln256_kernel<<<MBL / 8, 256>>>(p_xs, cnn_ln_g, cnn_ln_b, p_enc, 256, 0);

    for (int i = 0; i < NLAY; i++) {
        const float* Wo_i  = Wo + (long long)i * DD * DD;
        const float* Wf1_i = Wff1 + (long long)i * DFF * DD;
        const float* Wf2_i = Wff2 + (long long)i * DD * DFF;
        const float* bo_i = bo + i * DD;

        // fused QKV projection (tf32 TC): [MBL,256] x [256,768]
        tgemm128<0, false, EPI_BIAS><<<dim3(6, 512, 1), 128, TG_DYN_BYTES>>>(
            p_enc, p_wqkv + (long long)i * 196608, p_bqkv + i * 768, nullptr,
            p_qkv, MBL, 768, 256, 256, 768, 0, 0, 0);

        // fused Gram + wrapped-diagonal reduction -> rp[b][tau]
        cudaMemsetAsync(p_rp, 0, (size_t)BB * LLEN * sizeof(float));
        tgemm128<0, true, EPI_GRAM><<<dim3(8, 8, BB), 128, TG_DYN_BYTES>>>(
            p_qkv, p_qkv + 256, nullptr, nullptr, p_rp,
            LLEN, LLEN, 256, 768, 768, SLQ, SLQ, LLEN);
        topk_kernel<<<BB, 256>>>(p_rp, p_del, p_w);
        agg_kernel<<<dim3(LLEN / 4, BB), 256>>>(p_qkv, p_del, p_w, p_ac);

        // x = enc + (ac @ Wo + bo)
        tgemm128<0, false, EPI_BIAS | EPI_RES><<<dim3(2, 512, 1), 128, TG_DYN_BYTES>>>(
            p_ac, Wo_i, bo_i, p_enc, p_xs, MBL, DD, DD, 256, 256, 0, 0, 0);
        decomp_kernel<<<dim3(16, 4, BB), 256>>>(p_xs, p_xd);

        // FFN (tf32 TC)
        tgemm128<0, true, EPI_GELU><<<dim3(8, 512, 1), 128, TG_DYN_BYTES>>>(
            p_xd, Wf1_i, nullptr, nullptr, p_big, MBL, DFF, DD, 256, 256, 0, 0, 0);
        tgemm128<0, true, EPI_RES><<<dim3(2, 512, 1), 128, TG_DYN_BYTES>>>(
            p_big, Wf2_i, nullptr, p_xd, p_xs, MBL, DD, DFF, 1024, 1024, 0, 0, 0);
        decomp_kernel<<<dim3(16, 4, BB), 256>>>(p_xs, p_enc);

        pool_copy_kernel<<<BB, 256>>>(p_enc, p_final, i * DD);
    }

    // input embed LN into final feature buffer
    ln256_kernel<<<BB / 8, 256>>>(p_emb, proj_ln_g, proj_ln_b, p_final, NLAY * DD + HSZ, NLAY * DD);

    // regression head
    sgemm64<EPI_BIAS | EPI_RELU><<<dim3(4, 1), 256>>>(p_final, rp1_w, rp1_b, p_o1, BB, HSZ, NLAY * DD + HSZ);
    ln256_kernel<<<BB / 8, 256>>>(p_o1, rp_ln_g, rp_ln_b, p_o2, 256, 0);
    rp2_kernel<<<BB, 256>>>(p_o2, rp2_w, rp2_b, out);
}

// round 15
// speedup vs baseline: 1.4009x; 1.0259x over previous
#include <cuda_runtime.h>
#include <cuda_bf16.h>
#include <math.h>

// ---------------- static problem config ----------------
#define BB   64
#define LLEN 1024
#define CIN  16
#define DD   256
#define HH   8
#define DFF  1024
#define HSZ  256
#define NLAY 2
#define TOPK 20
#define MAW  25   // moving average window

// ---------------- device scratch (no allocs allowed) ----------------
__device__ __align__(16) float g_h1 [BB*LLEN*DD];            // conv1 out (tf32-rounded)
__device__ __align__(16) float g_enc[BB*LLEN*DD];            // encoder state
__device__ __align__(16) float g_qkv[BB*LLEN*768];           // fused q|k|v (q,k tf32-rounded)
__device__ __align__(16) float g_ac [BB*LLEN*DD];            // autocorr agg out (tf32-rounded)
__device__ __align__(16) float g_xs [BB*LLEN*DD];            // x (pre-decomp) / conv2 out
__device__ __align__(16) float g_xd [BB*LLEN*DD];            // x after decomp
__device__ __align__(16) float g_big[BB*LLEN*DFF];           // FFN hidden (tf32-rounded)
__device__ __align__(16) float g_rp [BB*LLEN];               // correlation sums per tau
__device__ int   g_del[BB*TOPK];
__device__ float g_w  [BB*TOPK];
__device__ __align__(16) float g_emb[BB*HSZ];
__device__ __align__(16) float g_final[BB*(NLAY*DD+HSZ)];    // [64][768]
__device__ __align__(16) float g_o1[BB*HSZ];
__device__ __align__(16) float g_o2[BB*HSZ];
__device__ __align__(16) float g_w2t[768*256];               // conv2 weights [K=768][N=256] (rounded)
__device__ __align__(16) float g_wqkv[NLAY*256*768];         // packed QKV weights (rounded)
__device__ __align__(16) float g_bqkv[NLAY*768];
__device__ __align__(16) float g_wo_r [NLAY*256*256];        // rounded Wo
__device__ __align__(16) float g_wf1_r[NLAY*DFF*256];        // rounded Wff1
__device__ __align__(16) float g_wf2_r[NLAY*256*DFF];        // rounded Wff2

// ---------------- epilogue flags ----------------
#define EPI_BIAS  1
#define EPI_RELU  2
#define EPI_GELU  4
#define EPI_RES   8
#define EPI_GRAM  16   // no C tile write; wrapped-diagonal reduce into C (=rp+b*1024)
#define EPI_RND   32   // tf32-round stored output
#define EPI_RNDQK 64   // tf32-round stored output only for global col < 512

__device__ __forceinline__ unsigned f2tf(float f) {
    unsigned u;
    asm("cvt.rna.tf32.f32 %0, %1;" : "=r"(u) : "f"(f));
    return u;
}
__device__ __forceinline__ float f2tf_f(float f) { return __uint_as_float(f2tf(f)); }

__device__ __forceinline__ void mma_tf32(float* c, const unsigned* a, const unsigned* b) {
    asm volatile(
        "mma.sync.aligned.m16n8k8.row.col.f32.tf32.tf32.f32 "
        "{%0,%1,%2,%3}, {%4,%5,%6,%7}, {%8,%9}, {%0,%1,%2,%3};\n"
        : "+f"(c[0]), "+f"(c[1]), "+f"(c[2]), "+f"(c[3])
        : "r"(a[0]), "r"(a[1]), "r"(a[2]), "r"(a[3]), "r"(b[0]), "r"(b[1]));
}

// 16B cp.async with zero-fill predicate (src_size = 0 -> all zeros)
__device__ __forceinline__ void cp16(unsigned smem_addr, const void* gptr, bool pred) {
    int sz = pred ? 16 : 0;
    asm volatile("cp.async.cg.shared.global [%0], [%1], 16, %2;\n"
                 :: "r"(smem_addr), "l"(gptr), "r"(sz));
}
__device__ __forceinline__ void cp_commit() {
    asm volatile("cp.async.commit_group;\n");
}
__device__ __forceinline__ void cp_wait0() {
    asm volatile("cp.async.wait_group 0;\n");
}

// =====================================================================
// tf32 tensor-core GEMM, 128x128x32 CTA tile, 128 threads (4 warps),
// warp tile 64x64 (warps 2 x 2), mma m16n8k8, 2-stage cp.async.
// RA: apply cvt.rna at A-fragment load (needed when the A buffer was not
//     pre-rounded). B operands are ALWAYS pre-rounded by producers, so
//     B fragments are consumed as raw bits -- bit-identical math,
//     fewer ALU instructions in the mma phase.
// =====================================================================
#define ASTRIDE 36
#define ASTG  (128 * ASTRIDE)     // 4608 floats per stage
#define BSTG  4608                // max(128*36, 32*136)
#define TG_DYN_BYTES (2 * (ASTG + BSTG) * 4)   // 73728

template<int AMODE, bool TB, int EPI, bool RA>
__global__ __launch_bounds__(128) void tgemm128(
    const float* __restrict__ A, const float* __restrict__ B,
    const float* __restrict__ bias, const float* __restrict__ res,
    float* __restrict__ C, int M, int N, int K, int lda, int ldb,
    long long sA, long long sB, long long sC)
{
    extern __shared__ float dynsm[];
    float* Asm = dynsm;               // 2 * ASTG
    float* Bsm = dynsm + 2 * ASTG;    // 2 * BSTG
    __shared__ float sdiag[256];
    long long bz = blockIdx.z;
    A += bz * sA;  B += bz * sB;  C += bz * sC;
    if (EPI & EPI_RES) res += bz * sC;

    int m0 = blockIdx.y * 128, n0 = blockIdx.x * 128;
    int t = threadIdx.x;
    int wid = t >> 5, lane = t & 31;
    int g = lane >> 2, t4 = lane & 3;
    int wm = (wid & 1) * 64;
    int wn = (wid >> 1) * 64;

    unsigned sA_u = (unsigned)__cvta_generic_to_shared(Asm);
    unsigned sB_u = (unsigned)__cvta_generic_to_shared(Bsm);

    float acc[4][8][4];
    #pragma unroll
    for (int mi = 0; mi < 4; mi++)
        #pragma unroll
        for (int ni = 0; ni < 8; ni++)
            #pragma unroll
            for (int r = 0; r < 4; r++) acc[mi][ni][r] = 0.f;

#define ISSUE_COPY(ST, K0)                                                     \
    {                                                                          \
        _Pragma("unroll")                                                      \
        for (int j = 0; j < 8; j++) {                                          \
            int c   = t + j * 128;                                             \
            int row = c >> 3;                                                  \
            int kc  = (c & 7) * 4;                                             \
            unsigned as = sA_u + ((ST) * ASTG + row * ASTRIDE + kc) * 4;       \
            if (AMODE == 0) {                                                  \
                cp16(as, A + (long long)(m0 + row) * lda + (K0) + kc, true);   \
            } else {                                                           \
                int kk = (K0) + kc;                                            \
                int sft = kk >> 8;                                             \
                int cc  = kk & 255;                                            \
                int ll  = m0 + row + sft - 1;                                  \
                bool ok = (ll >= 0 && ll < LLEN);                              \
                const float* gp = ok ? (A + (long long)ll * 256 + cc) : A;     \
                cp16(as, gp, ok);                                              \
            }                                                                  \
        }                                                                      \
        _Pragma("unroll")                                                      \
        for (int j = 0; j < 8; j++) {                                          \
            int c = t + j * 128;                                               \
            if (TB) {                                                          \
                int n   = c >> 3;                                              \
                int kc  = (c & 7) * 4;                                         \
                unsigned bs = sB_u + ((ST) * BSTG + n * ASTRIDE + kc) * 4;     \
                cp16(bs, B + (long long)(n0 + n) * ldb + (K0) + kc, true);     \
            } else {                                                           \
                int bk = c >> 5;                                               \
                int bn = (c & 31) * 4;                                         \
                unsigned bs = sB_u + ((ST) * BSTG + bk * 136 + bn) * 4;        \
                cp16(bs, B + (long long)((K0) + bk) * ldb + n0 + bn, true);    \
            }                                                                  \
        }                                                                      \
    }

    const int KT = K / 32;
    ISSUE_COPY(0, 0);
    cp_commit();

    const unsigned* Asmu = (const unsigned*)Asm;
    const unsigned* Bsmu = (const unsigned*)Bsm;

    for (int it = 0; it < KT; it++) {
        cp_wait0();
        __syncthreads();
        if (it + 1 < KT) ISSUE_COPY((it + 1) & 1, (it + 1) * 32);
        cp_commit();

        const float*    As   = Asm  + (it & 1) * ASTG;
        const unsigned* Asu  = Asmu + (it & 1) * ASTG;
        const unsigned* Bsu  = Bsmu + (it & 1) * BSTG;

        #pragma unroll
        for (int ks = 0; ks < 4; ks++) {
            int k0f = ks * 8 + t4;
            unsigned afr[4][4], bfr[8][2];
            #pragma unroll
            for (int mi = 0; mi < 4; mi++) {
                int mr = wm + mi * 16 + g;
                if (RA) {
                    afr[mi][0] = f2tf(As[mr * ASTRIDE + k0f]);
                    afr[mi][1] = f2tf(As[(mr + 8) * ASTRIDE + k0f]);
                    afr[mi][2] = f2tf(As[mr * ASTRIDE + k0f + 4]);
                    afr[mi][3] = f2tf(As[(mr + 8) * ASTRIDE + k0f + 4]);
                } else {
                    afr[mi][0] = Asu[mr * ASTRIDE + k0f];
                    afr[mi][1] = Asu[(mr + 8) * ASTRIDE + k0f];
                    afr[mi][2] = Asu[mr * ASTRIDE + k0f + 4];
                    afr[mi][3] = Asu[(mr + 8) * ASTRIDE + k0f + 4];
                }
            }
            #pragma unroll
            for (int ni = 0; ni < 8; ni++) {
                int nc = wn + ni * 8 + g;
                if (TB) {
                    bfr[ni][0] = Bsu[nc * ASTRIDE + k0f];
                    bfr[ni][1] = Bsu[nc * ASTRIDE + k0f + 4];
                } else {
                    bfr[ni][0] = Bsu[k0f * 136 + nc];
                    bfr[ni][1] = Bsu[(k0f + 4) * 136 + nc];
                }
            }
            #pragma unroll
            for (int mi = 0; mi < 4; mi++)
                #pragma unroll
                for (int ni = 0; ni < 8; ni++)
                    mma_tf32(acc[mi][ni], afr[mi], bfr[ni]);
        }
        __syncthreads();
    }
#undef ISSUE_COPY

    if (EPI & EPI_GRAM) {
        sdiag[t] = 0.f;
        sdiag[t + 128] = 0.f;
        __syncthreads();
        #pragma unroll
        for (int mi = 0; mi < 4; mi++) {
            #pragma unroll
            for (int ni = 0; ni < 8; ni++) {
                int li0 = wm + mi * 16 + g;
                int lj0 = wn + ni * 8 + t4 * 2;
                #pragma unroll
                for (int half = 0; half < 2; half++) {
                    int li = li0 + half * 8;
                    atomicAdd(&sdiag[li - lj0 + 127],     acc[mi][ni][half * 2 + 0]);
                    atomicAdd(&sdiag[li - (lj0+1) + 127], acc[mi][ni][half * 2 + 1]);
                }
            }
        }
        __syncthreads();
        for (int i = t; i < 255; i += 128) {
            int tau = (m0 - n0 - 127 + i) & (LLEN - 1);
            atomicAdd(&C[tau], sdiag[i]);
        }
        return;
    }

    #pragma unroll
    for (int mi = 0; mi < 4; mi++) {
        #pragma unroll
        for (int ni = 0; ni < 8; ni++) {
            long long row0 = m0 + wm + mi * 16 + g;
            int col0 = n0 + wn + ni * 8 + t4 * 2;
            #pragma unroll
            for (int half = 0; half < 2; half++) {
                long long gm = row0 + half * 8;
                float v0 = acc[mi][ni][half * 2 + 0];
                float v1 = acc[mi][ni][half * 2 + 1];
                if (EPI & EPI_BIAS) { v0 += bias[col0]; v1 += bias[col0 + 1]; }
                if (EPI & EPI_RELU) { v0 = fmaxf(v0, 0.f); v1 = fmaxf(v1, 0.f); }
                if (EPI & EPI_GELU) {
                    v0 = 0.5f * v0 * (1.f + erff(v0 * 0.70710678118654752f));
                    v1 = 0.5f * v1 * (1.f + erff(v1 * 0.70710678118654752f));
                }
                if (EPI & EPI_RES) {
                    v0 += res[gm * N + col0];
                    v1 += res[gm * N + col0 + 1];
                }
                if (EPI & EPI_RND) { v0 = f2tf_f(v0); v1 = f2tf_f(v1); }
                if (EPI & EPI_RNDQK) {
                    if (col0 < 512) { v0 = f2tf_f(v0); v1 = f2tf_f(v1); }
                }
                *(float2*)(C + gm * N + col0) = make_float2(v0, v1);
            }
        }
    }
}

// grid-stride tf32 round-copy (for weight operands)
__global__ void rnd_copy_kernel(const float* __restrict__ src, float* __restrict__ dst, int n)
{
    for (int i = blockIdx.x * 256 + threadIdx.x; i < n; i += gridDim.x * 256)
        dst[i] = f2tf_f(src[i]);
}

// transpose conv2 weights [D=256][C=256][3] -> [K=768 (j*256+c)][D=256], rounded
__global__ void w2t_kernel(const float* __restrict__ w, float* __restrict__ o)
{
    int i = blockIdx.x * 256 + threadIdx.x;
    int d  = i & 255;
    int kk = i >> 8;
    int c  = kk & 255;
    int j  = kk >> 8;
    o[(long long)kk * 256 + d] = f2tf_f(w[(long long)d * 768 + c * 3 + j]);
}

// pack QKV weights: [lay][K=256][N=768] where N segment 0/1/2 = Wq/Wk/Wv, rounded
__global__ void packqkv_kernel(
    const float* __restrict__ Wq, const float* __restrict__ Wk,
    const float* __restrict__ Wv, const float* __restrict__ bq,
    const float* __restrict__ bk, const float* __restrict__ bv,
    float* __restrict__ wout, float* __restrict__ bout)
{
    long long i = (long long)blockIdx.x * 256 + threadIdx.x;   // NLAY*256*768
    int lay = (int)(i / 196608);
    int j   = (int)(i - (long long)lay * 196608);
    int k   = j / 768;
    int n   = j - k * 768;
    int seg = n >> 8, col = n & 255;
    const float* W = (seg == 0) ? Wq : (seg == 1) ? Wk : Wv;
    wout[i] = f2tf_f(W[(long long)lay * 65536 + k * 256 + col]);
    if (j < 768) {
        const float* bb = (seg == 0) ? bq : (seg == 1) ? bk : bv;
        bout[lay * 768 + j] = bb[lay * 256 + col];
    }
}

// 64x64x16 fp32 tile version for small-M GEMMs (M=64). B is [K,N] only.
template<int EPI>
__global__ __launch_bounds__(256) void sgemm64(
    const float* __restrict__ A, const float* __restrict__ B,
    const float* __restrict__ bias, float* __restrict__ C,
    int M, int N, int K)
{
    __shared__ float As[16][64];
    __shared__ float Bs[16][64];
    int m0 = blockIdx.y * 64, n0 = blockIdx.x * 64;
    int t = threadIdx.x;
    int tx = t & 15, ty = t >> 4;
    float acc[4][4];
    #pragma unroll
    for (int i = 0; i < 4; i++)
        #pragma unroll
        for (int j = 0; j < 4; j++) acc[i][j] = 0.f;

    const int am = t >> 2, ak = (t & 3) * 4;
    const int bk = t >> 4, bn = (t & 15) * 4;

    for (int k0 = 0; k0 < K; k0 += 16) {
        float4 av = *(const float4*)(A + (long long)(m0 + am) * K + k0 + ak);
        As[ak + 0][am] = av.x; As[ak + 1][am] = av.y;
        As[ak + 2][am] = av.z; As[ak + 3][am] = av.w;
        *(float4*)&Bs[bk][bn] = *(const float4*)(B + (long long)(k0 + bk) * N + n0 + bn);
        __syncthreads();
        #pragma unroll
        for (int kk = 0; kk < 16; kk++) {
            float4 a4 = *(const float4*)&As[kk][ty * 4];
            float4 b4 = *(const float4*)&Bs[kk][tx * 4];
            float a[4] = {a4.x, a4.y, a4.z, a4.w};
            float b[4] = {b4.x, b4.y, b4.z, b4.w};
            #pragma unroll
            for (int i = 0; i < 4; i++)
                #pragma unroll
                for (int j = 0; j < 4; j++)
                    acc[i][j] += a[i] * b[j];
        }
        __syncthreads();
    }
    #pragma unroll
    for (int i = 0; i < 4; i++) {
        long long gm = m0 + ty * 4 + i;
        float vr[4];
        #pragma unroll
        for (int j = 0; j < 4; j++) {
            int gn = n0 + tx * 4 + j;
            float v = acc[i][j];
            if (EPI & EPI_BIAS) v += bias[gn];
            if (EPI & EPI_RELU) v = fmaxf(v, 0.f);
            vr[j] = v;
        }
        *(float4*)(C + gm * N + n0 + tx * 4) = make_float4(vr[0], vr[1], vr[2], vr[3]);
    }
}

// =====================================================================
// conv1: [B,L,16] -> relu(conv1d k=3 pad=1) -> [B,L,256] (tf32-rounded:
// h1 is consumed only by the conv2 GEMM A-side)
// =====================================================================
__global__ __launch_bounds__(256) void conv1_kernel(
    const float* __restrict__ x, const float* __restrict__ w,
    const float* __restrict__ bias, float* __restrict__ out)
{
    int b = blockIdx.y, l0 = blockIdx.x * 16, d = threadIdx.x;
    __shared__ float sx[18][16];
    for (int idx = d; idx < 18 * 16; idx += 256) {
        int r = idx >> 4, c = idx & 15;
        int ll = l0 - 1 + r;
        sx[r][c] = (ll >= 0 && ll < LLEN) ? x[((long long)b * LLEN + ll) * CIN + c] : 0.f;
    }
    __syncthreads();
    float wreg[48];
    #pragma unroll
    for (int i = 0; i < 48; i++) wreg[i] = w[d * 48 + i];
    float bd = bias[d];
    #pragma unroll 4
    for (int i = 0; i < 16; i++) {
        float acc = bd;
        #pragma unroll
        for (int c = 0; c < 16; c++)
            #pragma unroll
            for (int j = 0; j < 3; j++)
                acc += sx[i + j][c] * wreg[c * 3 + j];
        out[((long long)b * LLEN + l0 + i) * DD + d] = f2tf_f(fmaxf(acc, 0.f));
    }
}

// =====================================================================
// LayerNorm over last dim = 256. 8 rows/block, 32 lanes/row, shuffle.
// =====================================================================
__global__ __launch_bounds__(256) void ln256_kernel(
    const float* __restrict__ in, const float* __restrict__ g,
    const float* __restrict__ bt, float* __restrict__ out,
    long long ostride, long long ooff)
{
    int t = threadIdx.x;
    int lane = t & 31, wr = t >> 5;
    long long r = (long long)blockIdx.x * 8 + wr;
    const float* ip = in + r * 256 + lane * 8;
    float4 v0 = *(const float4*)ip;
    float4 v1 = *(const float4*)(ip + 4);
    float x[8] = {v0.x, v0.y, v0.z, v0.w, v1.x, v1.y, v1.z, v1.w};
    float s = 0.f;
    #pragma unroll
    for (int j = 0; j < 8; j++) s += x[j];
    #pragma unroll
    for (int o = 16; o; o >>= 1) s += __shfl_xor_sync(0xFFFFFFFFu, s, o);
    float mean = s * (1.f / 256.f);
    float vs = 0.f;
    #pragma unroll
    for (int j = 0; j < 8; j++) { x[j] -= mean; vs += x[j] * x[j]; }
    #pragma unroll
    for (int o = 16; o; o >>= 1) vs += __shfl_xor_sync(0xFFFFFFFFu, vs, o);
    float inv = rsqrtf(vs * (1.f / 256.f) + 1e-5f);
    float4 g0 = *(const float4*)(g + lane * 8);
    float4 g1 = *(const float4*)(g + lane * 8 + 4);
    float4 b0 = *(const float4*)(bt + lane * 8);
    float4 b1 = *(const float4*)(bt + lane * 8 + 4);
    float gg[8] = {g0.x, g0.y, g0.z, g0.w, g1.x, g1.y, g1.z, g1.w};
    float bb[8] = {b0.x, b0.y, b0.z, b0.w, b1.x, b1.y, b1.z, b1.w};
    float o8[8];
    #pragma unroll
    for (int j = 0; j < 8; j++) o8[j] = x[j] * inv * gg[j] + bb[j];
    float* op = out + r * ostride + ooff + lane * 8;
    *(float4*)op       = make_float4(o8[0], o8[1], o8[2], o8[3]);
    *(float4*)(op + 4) = make_float4(o8[4], o8[5], o8[6], o8[7]);
}

// =====================================================================
// top-k(20) + softmax (ties -> lowest index, matches lax.top_k)
// =====================================================================
__global__ __launch_bounds__(256) void topk_kernel(
    const float* __restrict__ rp, int* __restrict__ del, float* __restrict__ wts)
{
    int b = blockIdx.x, t = threadIdx.x;
    __shared__ float sv[LLEN];
    __shared__ float rv[256];
    __shared__ int   ri[256];
    __shared__ float selv[TOPK];
    __shared__ int   seli[TOPK];
    for (int i = t; i < LLEN; i += 256)
        sv[i] = rp[(long long)b * LLEN + i] * (1.f / 256.f);
    __syncthreads();
    for (int iter = 0; iter < TOPK; iter++) {
        float bv = -INFINITY; int bi = 1 << 30;
        for (int i = t; i < LLEN; i += 256) {
            float v = sv[i];
            if (v > bv || (v == bv && i < bi)) { bv = v; bi = i; }
        }
        rv[t] = bv; ri[t] = bi; __syncthreads();
        for (int s = 128; s > 0; s >>= 1) {
            if (t < s) {
                if (rv[t + s] > rv[t] || (rv[t + s] == rv[t] && ri[t + s] < ri[t])) {
                    rv[t] = rv[t + s]; ri[t] = ri[t + s];
                }
            }
            __syncthreads();
        }
        if (t == 0) { selv[iter] = rv[0]; seli[iter] = ri[0]; sv[ri[0]] = -INFINITY; }
        __syncthreads();
    }
    if (t == 0) {
        float m = selv[0];
        float e[TOPK], ssum = 0.f;
        for (int k2 = 0; k2 < TOPK; k2++) { e[k2] = expf(selv[k2] - m); ssum += e[k2]; }
        float inv = 1.f / ssum;
        for (int k2 = 0; k2 < TOPK; k2++) {
            wts[b * TOPK + k2] = e[k2] * inv;
            del[b * TOPK + k2] = seli[k2];
        }
    }
}

// =====================================================================
// delayed aggregation: out[b,l,d] = sum_k w[k] * V[b,(l+delay[k])%L,d]
// V = qkv + 512, row stride 768. Output tf32-rounded (feeds only Wo GEMM A).
// =====================================================================
__global__ __launch_bounds__(256) void agg_kernel(
    const float* __restrict__ QKV, const int* __restrict__ del,
    const float* __restrict__ wts, float* __restrict__ out)
{
    int t = threadIdx.x;
    int b = blockIdx.y;
    int l = blockIdx.x * 4 + (t >> 6);
    int d4 = (t & 63) * 4;
    __shared__ int   sd[TOPK];
    __shared__ float sw[TOPK];
    if (t < TOPK) { sd[t] = del[b * TOPK + t]; sw[t] = wts[b * TOPK + t]; }
    __syncthreads();
    const float* vb = QKV + (long long)b * LLEN * 768 + 512;
    float a0 = 0.f, a1 = 0.f, a2 = 0.f, a3 = 0.f;
    #pragma unroll
    for (int k2 = 0; k2 < TOPK; k2++) {
        float w = sw[k2];
        float4 v = *(const float4*)(vb + (long long)((l + sd[k2]) & (LLEN - 1)) * 768 + d4);
        a0 += w * v.x; a1 += w * v.y; a2 += w * v.z; a3 += w * v.w;
    }
    *(float4*)(out + ((long long)b * LLEN + l) * DD + d4) =
        make_float4(f2tf_f(a0), f2tf_f(a1), f2tf_f(a2), f2tf_f(a3));
}

// =====================================================================
// series decomposition: out = in - movavg25(in, replicate-pad)
// =====================================================================
__global__ __launch_bounds__(256) void decomp_kernel(
    const float* __restrict__ in, float* __restrict__ out)
{
    __shared__ float s[88][65];
    int b  = blockIdx.z;
    int c0 = blockIdx.y * 64;
    int l0 = blockIdx.x * 64;
    int t  = threadIdx.x;
    const float* base = in + (long long)b * LLEN * DD;
    for (int idx = t; idx < 88 * 64; idx += 256) {
        int r = idx >> 6, c = idx & 63;
        int ll = l0 - 12 + r;
        ll = max(0, min(LLEN - 1, ll));
        s[r][c] = base[(long long)ll * DD + c0 + c];
    }
    __syncthreads();
    int c = t & 63, lg = t >> 6;
    int lbase = lg * 16;
    float sum = 0.f;
    #pragma unroll
    for (int r = 0; r < MAW; r++) sum += s[lbase + r][c];
    float* ob = out + (long long)b * LLEN * DD;
    ob[(long long)(l0 + lbase) * DD + c0 + c] = s[lbase + 12][c] - sum * (1.f / MAW);
    #pragma unroll
    for (int i = 1; i < 16; i++) {
        sum += s[lbase + i + 24][c] - s[lbase + i - 1][c];
        ob[(long long)(l0 + lbase + i) * DD + c0 + c] = s[lbase + i + 12][c] - sum * (1.f / MAW);
    }
}

__global__ void pool_copy_kernel(const float* __restrict__ enc, float* __restrict__ fin, int off)
{
    int b = blockIdx.x, d = threadIdx.x;
    fin[b * (NLAY * DD + HSZ) + off + d] = enc[((long long)b * LLEN + (LLEN - 1)) * DD + d];
}

__global__ __launch_bounds__(256) void rp2_kernel(
    const float* __restrict__ o2, const float* __restrict__ w,
    const float* __restrict__ bias, float* __restrict__ out)
{
    int b = blockIdx.x, t = threadIdx.x;
    __shared__ float red[256];
    red[t] = o2[b * 256 + t] * w[t];
    __syncthreads();
    for (int s = 128; s > 0; s >>= 1) { if (t < s) red[t] += red[t + s]; __syncthreads(); }
    if (t == 0) out[b] = red[0] + bias[0];
}

// =====================================================================
// launch
// =====================================================================
extern "C" void kernel_launch(void* const* d_in, const int* in_sizes, int n_in,
                              void* d_out, int out_size)
{
    (void)in_sizes; (void)n_in; (void)out_size;
    const float* x_enc     = (const float*)d_in[0];
    const float* conv1_w   = (const float*)d_in[1];
    const float* conv1_b   = (const float*)d_in[2];
    const float* conv2_w   = (const float*)d_in[3];
    const float* conv2_b   = (const float*)d_in[4];
    const float* cnn_ln_g  = (const float*)d_in[5];
    const float* cnn_ln_b  = (const float*)d_in[6];
    const float* proj_w    = (const float*)d_in[7];
    const float* proj_b    = (const float*)d_in[8];
    const float* proj_ln_g = (const float*)d_in[9];
    const float* proj_ln_b = (const float*)d_in[10];
    const float* Wq        = (const float*)d_in[11];
    const float* bq        = (const float*)d_in[12];
    const float* Wk        = (const float*)d_in[13];
    const float* bk        = (const float*)d_in[14];
    const float* Wv        = (const float*)d_in[15];
    const float* bv        = (const float*)d_in[16];
    const float* Wo        = (const float*)d_in[17];
    const float* bo        = (const float*)d_in[18];
    const float* Wff1      = (const float*)d_in[19];
    const float* Wff2      = (const float*)d_in[20];
    const float* rp1_w     = (const float*)d_in[21];
    const float* rp1_b     = (const float*)d_in[22];
    const float* rp_ln_g   = (const float*)d_in[23];
    const float* rp_ln_b   = (const float*)d_in[24];
    const float* rp2_w     = (const float*)d_in[25];
    const float* rp2_b     = (const float*)d_in[26];
    float* out = (float*)d_out;

    float *p_h1, *p_enc, *p_qkv, *p_ac, *p_xs, *p_xd, *p_big, *p_rp;
    float *p_emb, *p_final, *p_o1, *p_o2, *p_w, *p_w2t, *p_wqkv, *p_bqkv;
    float *p_wo, *p_wf1, *p_wf2;
    int* p_del;
    cudaGetSymbolAddress((void**)&p_h1,  g_h1);
    cudaGetSymbolAddress((void**)&p_enc, g_enc);
    cudaGetSymbolAddress((void**)&p_qkv, g_qkv);
    cudaGetSymbolAddress((void**)&p_ac,  g_ac);
    cudaGetSymbolAddress((void**)&p_xs,  g_xs);
    cudaGetSymbolAddress((void**)&p_xd,  g_xd);
    cudaGetSymbolAddress((void**)&p_big, g_big);
    cudaGetSymbolAddress((void**)&p_rp,  g_rp);
    cudaGetSymbolAddress((void**)&p_del, g_del);
    cudaGetSymbolAddress((void**)&p_w,   g_w);
    cudaGetSymbolAddress((void**)&p_emb, g_emb);
    cudaGetSymbolAddress((void**)&p_final, g_final);
    cudaGetSymbolAddress((void**)&p_o1,  g_o1);
    cudaGetSymbolAddress((void**)&p_o2,  g_o2);
    cudaGetSymbolAddress((void**)&p_w2t, g_w2t);
    cudaGetSymbolAddress((void**)&p_wqkv, g_wqkv);
    cudaGetSymbolAddress((void**)&p_bqkv, g_bqkv);
    cudaGetSymbolAddress((void**)&p_wo,  g_wo_r);
    cudaGetSymbolAddress((void**)&p_wf1, g_wf1_r);
    cudaGetSymbolAddress((void**)&p_wf2, g_wf2_r);

    const int MBL = BB * LLEN;  // 65536
    const long long SLD = (long long)LLEN * DD;
    const long long SLQ = (long long)LLEN * 768;

    // opt-in to 72KB dynamic smem for every tgemm instantiation
    cudaFuncSetAttribute(tgemm128<1, false, EPI_BIAS | EPI_RELU, false>, cudaFuncAttributeMaxDynamicSharedMemorySize, TG_DYN_BYTES);
    cudaFuncSetAttribute(tgemm128<0, false, EPI_BIAS | EPI_RNDQK, true>, cudaFuncAttributeMaxDynamicSharedMemorySize, TG_DYN_BYTES);
    cudaFuncSetAttribute(tgemm128<0, true,  EPI_GRAM, false>,            cudaFuncAttributeMaxDynamicSharedMemorySize, TG_DYN_BYTES);
    cudaFuncSetAttribute(tgemm128<0, false, EPI_BIAS | EPI_RES, false>,  cudaFuncAttributeMaxDynamicSharedMemorySize, TG_DYN_BYTES);
    cudaFuncSetAttribute(tgemm128<0, true,  EPI_GELU | EPI_RND, true>,   cudaFuncAttributeMaxDynamicSharedMemorySize, TG_DYN_BYTES);
    cudaFuncSetAttribute(tgemm128<0, true,  EPI_RES, false>,             cudaFuncAttributeMaxDynamicSharedMemorySize, TG_DYN_BYTES);

    // prep + frontend (weight rounding is exact-math: weights feed only GEMMs)
    w2t_kernel<<<768, 256>>>(conv2_w, p_w2t);
    packqkv_kernel<<<NLAY * 768, 256>>>(Wq, Wk, Wv, bq, bk, bv, p_wqkv, p_bqkv);
    rnd_copy_kernel<<<512, 256>>>(Wo,   p_wo,  NLAY * 256 * 256);
    rnd_copy_kernel<<<2048, 256>>>(Wff1, p_wf1, NLAY * DFF * 256);
    rnd_copy_kernel<<<2048, 256>>>(Wff2, p_wf2, NLAY * 256 * DFF);
    conv1_kernel<<<dim3(LLEN / 16, BB), 256>>>(x_enc, conv1_w, conv1_b, p_h1);
    tgemm128<1, false, EPI_BIAS | EPI_RELU, false><<<dim3(2, 8, BB), 128, TG_DYN_BYTES>>>(
        p_h1, p_w2t, conv2_b, nullptr, p_xs, LLEN, DD, 768, 256, 256, SLD, 0, SLD);
    sgemm64<EPI_BIAS | EPI_RELU><<<dim3(4, 1), 256>>>(x_enc, proj_w, proj_b, p_emb, BB, HSZ, LLEN * CIN);
    ln256_kernel<<<MBL / 8, 256>>>(p_xs, cnn_ln_g, cnn_ln_b, p_enc, 256, 0);

    for (int i = 0; i < NLAY; i++) {
        const float* Wo_i  = p_wo  + (long long)i * DD * DD;
        const float* Wf1_i = p_wf1 + (long long)i * DFF * DD;
        const float* Wf2_i = p_wf2 + (long long)i * DD * DFF;
        const float* bo_i = bo + i * DD;

        // fused QKV projection; Q,K columns tf32-rounded at store (feed only Gram)
        tgemm128<0, false, EPI_BIAS | EPI_RNDQK, true><<<dim3(6, 512, 1), 128, TG_DYN_BYTES>>>(
            p_enc, p_wqkv + (long long)i * 196608, p_bqkv + i * 768, nullptr,
            p_qkv, MBL, 768, 256, 256, 768, 0, 0, 0);

        // fused Gram + wrapped-diagonal reduction -> rp[b][tau]
        cudaMemsetAsync(p_rp, 0, (size_t)BB * LLEN * sizeof(float));
        tgemm128<0, true, EPI_GRAM, false><<<dim3(8, 8, BB), 128, TG_DYN_BYTES>>>(
            p_qkv, p_qkv + 256, nullptr, nullptr, p_rp,
            LLEN, LLEN, 256, 768, 768, SLQ, SLQ, LLEN);
        topk_kernel<<<BB, 256>>>(p_rp, p_del, p_w);
        agg_kernel<<<dim3(LLEN / 4, BB), 256>>>(p_qkv, p_del, p_w, p_ac);

        // x = enc + (ac @ Wo + bo)
        tgemm128<0, false, EPI_BIAS | EPI_RES, false><<<dim3(2, 512, 1), 128, TG_DYN_BYTES>>>(
            p_ac, Wo_i, bo_i, p_enc, p_xs, MBL, DD, DD, 256, 256, 0, 0, 0);
        decomp_kernel<<<dim3(16, 4, BB), 256>>>(p_xs, p_xd);

        // FFN (tf32 TC); FFN1 output rounded (feeds only FFN2 A-side)
        tgemm128<0, true, EPI_GELU | EPI_RND, true><<<dim3(8, 512, 1), 128, TG_DYN_BYTES>>>(
            p_xd, Wf1_i, nullptr, nullptr, p_big, MBL, DFF, DD, 256, 256, 0, 0, 0);
        tgemm128<0, true, EPI_RES, false><<<dim3(2, 512, 1), 128, TG_DYN_BYTES>>>(
            p_big, Wf2_i, nullptr, p_xd, p_xs, MBL, DD, DFF, 1024, 1024, 0, 0, 0);
        decomp_kernel<<<dim3(16, 4, BB), 256>>>(p_xs, p_enc);

        pool_copy_kernel<<<BB, 256>>>(p_enc, p_final, i * DD);
    }

    // input embed LN into final feature buffer
    ln256_kernel<<<BB / 8, 256>>>(p_emb, proj_ln_g, proj_ln_b, p_final, NLAY * DD + HSZ, NLAY * DD);

    // regression head
    sgemm64<EPI_BIAS | EPI_RELU><<<dim3(4, 1), 256>>>(p_final, rp1_w, rp1_b, p_o1, BB, HSZ, NLAY * DD + HSZ);
    ln256_kernel<<<BB / 8, 256>>>(p_o1, rp_ln_g, rp_ln_b, p_o2, 256, 0);
    rp2_kernel<<<BB, 256>>>(p_o2, rp2_w, rp2_b, out);
}

// round 16
// speedup vs baseline: 1.8750x; 1.3384x over previous
#include <cuda_runtime.h>
#include <cuda_bf16.h>
#include <math.h>

// ---------------- static problem config ----------------
#define BB   64
#define LLEN 1024
#define CIN  16
#define DD   256
#define HH   8
#define DFF  1024
#define HSZ  256
#define NLAY 2
#define TOPK 20
#define MAW  25   // moving average window

// ---------------- device scratch (no allocs allowed) ----------------
__device__ __align__(16) float g_h1 [BB*LLEN*DD];            // conv1 out (tf32-rounded)
__device__ __align__(16) float g_enc[BB*LLEN*DD];            // encoder state
__device__ __align__(16) float g_qkv[BB*LLEN*768];           // fused q|k|v (q,k tf32-rounded)
__device__ __align__(16) float g_ac [BB*LLEN*DD];            // autocorr agg out (tf32-rounded)
__device__ __align__(16) float g_xs [BB*LLEN*DD];            // x (pre-decomp) / conv2 out
__device__ __align__(16) float g_xd [BB*LLEN*DD];            // x after decomp
__device__ __align__(16) float g_big[BB*LLEN*DFF];           // FFN hidden (tf32-rounded)
__device__ __align__(16) float g_rp [BB*LLEN];               // correlation sums per tau
__device__ int   g_del[BB*TOPK];
__device__ float g_w  [BB*TOPK];
__device__ __align__(16) float g_emb[BB*HSZ];                // raw proj sums (pre bias/relu)
__device__ __align__(16) float g_final[BB*(NLAY*DD+HSZ)];    // [64][768]
__device__ __align__(16) float g_o1[BB*HSZ];
__device__ __align__(16) float g_o2[BB*HSZ];
__device__ __align__(16) float g_w2t[768*256];               // conv2 weights [K=768][N=256] (rounded)
__device__ __align__(16) float g_wqkv[NLAY*256*768];         // packed QKV weights (rounded)
__device__ __align__(16) float g_bqkv[NLAY*768];
__device__ __align__(16) float g_wo_r [NLAY*256*256];        // rounded Wo
__device__ __align__(16) float g_wf1_r[NLAY*DFF*256];        // rounded Wff1
__device__ __align__(16) float g_wf2_r[NLAY*256*DFF];        // rounded Wff2

// ---------------- epilogue flags ----------------
#define EPI_BIAS  1
#define EPI_RELU  2
#define EPI_GELU  4
#define EPI_RES   8
#define EPI_GRAM  16   // no C tile write; wrapped-diagonal reduce into C (=rp+b*1024)
#define EPI_RND   32   // tf32-round stored output
#define EPI_RNDQK 64   // tf32-round stored output only for global col < 512

__device__ __forceinline__ unsigned f2tf(float f) {
    unsigned u;
    asm("cvt.rna.tf32.f32 %0, %1;" : "=r"(u) : "f"(f));
    return u;
}
__device__ __forceinline__ float f2tf_f(float f) { return __uint_as_float(f2tf(f)); }

__device__ __forceinline__ void mma_tf32(float* c, const unsigned* a, const unsigned* b) {
    asm volatile(
        "mma.sync.aligned.m16n8k8.row.col.f32.tf32.tf32.f32 "
        "{%0,%1,%2,%3}, {%4,%5,%6,%7}, {%8,%9}, {%0,%1,%2,%3};\n"
        : "+f"(c[0]), "+f"(c[1]), "+f"(c[2]), "+f"(c[3])
        : "r"(a[0]), "r"(a[1]), "r"(a[2]), "r"(a[3]), "r"(b[0]), "r"(b[1]));
}

// 16B cp.async with zero-fill predicate (src_size = 0 -> all zeros)
__device__ __forceinline__ void cp16(unsigned smem_addr, const void* gptr, bool pred) {
    int sz = pred ? 16 : 0;
    asm volatile("cp.async.cg.shared.global [%0], [%1], 16, %2;\n"
                 :: "r"(smem_addr), "l"(gptr), "r"(sz));
}
__device__ __forceinline__ void cp_commit() {
    asm volatile("cp.async.commit_group;\n");
}
__device__ __forceinline__ void cp_wait0() {
    asm volatile("cp.async.wait_group 0;\n");
}

// =====================================================================
// tf32 tensor-core GEMM, 128x128x32 CTA tile, 128 threads (4 warps),
// warp tile 64x64 (warps 2 x 2), mma m16n8k8, 2-stage cp.async.
// RA: apply cvt.rna at A-fragment load (only for non-pre-rounded A).
// B operands are ALWAYS pre-rounded by producers.
// =====================================================================
#define ASTRIDE 36
#define ASTG  (128 * ASTRIDE)     // 4608 floats per stage
#define BSTG  4608                // max(128*36, 32*136)
#define TG_DYN_BYTES (2 * (ASTG + BSTG) * 4)   // 73728

template<int AMODE, bool TB, int EPI, bool RA>
__global__ __launch_bounds__(128) void tgemm128(
    const float* __restrict__ A, const float* __restrict__ B,
    const float* __restrict__ bias, const float* __restrict__ res,
    float* __restrict__ C, int M, int N, int K, int lda, int ldb,
    long long sA, long long sB, long long sC)
{
    extern __shared__ float dynsm[];
    float* Asm = dynsm;               // 2 * ASTG
    float* Bsm = dynsm + 2 * ASTG;    // 2 * BSTG
    __shared__ float sdiag[256];
    long long bz = blockIdx.z;
    A += bz * sA;  B += bz * sB;  C += bz * sC;
    if (EPI & EPI_RES) res += bz * sC;

    int m0 = blockIdx.y * 128, n0 = blockIdx.x * 128;
    int t = threadIdx.x;
    int wid = t >> 5, lane = t & 31;
    int g = lane >> 2, t4 = lane & 3;
    int wm = (wid & 1) * 64;
    int wn = (wid >> 1) * 64;

    unsigned sA_u = (unsigned)__cvta_generic_to_shared(Asm);
    unsigned sB_u = (unsigned)__cvta_generic_to_shared(Bsm);

    float acc[4][8][4];
    #pragma unroll
    for (int mi = 0; mi < 4; mi++)
        #pragma unroll
        for (int ni = 0; ni < 8; ni++)
            #pragma unroll
            for (int r = 0; r < 4; r++) acc[mi][ni][r] = 0.f;

#define ISSUE_COPY(ST, K0)                                                     \
    {                                                                          \
        _Pragma("unroll")                                                      \
        for (int j = 0; j < 8; j++) {                                          \
            int c   = t + j * 128;                                             \
            int row = c >> 3;                                                  \
            int kc  = (c & 7) * 4;                                             \
            unsigned as = sA_u + ((ST) * ASTG + row * ASTRIDE + kc) * 4;       \
            if (AMODE == 0) {                                                  \
                cp16(as, A + (long long)(m0 + row) * lda + (K0) + kc, true);   \
            } else {                                                           \
                int kk = (K0) + kc;                                            \
                int sft = kk >> 8;                                             \
                int cc  = kk & 255;                                            \
                int ll  = m0 + row + sft - 1;                                  \
                bool ok = (ll >= 0 && ll < LLEN);                              \
                const float* gp = ok ? (A + (long long)ll * 256 + cc) : A;     \
                cp16(as, gp, ok);                                              \
            }                                                                  \
        }                                                                      \
        _Pragma("unroll")                                                      \
        for (int j = 0; j < 8; j++) {                                          \
            int c = t + j * 128;                                               \
            if (TB) {                                                          \
                int n   = c >> 3;                                              \
                int kc  = (c & 7) * 4;                                         \
                unsigned bs = sB_u + ((ST) * BSTG + n * ASTRIDE + kc) * 4;     \
                cp16(bs, B + (long long)(n0 + n) * ldb + (K0) + kc, true);     \
            } else {                                                           \
                int bk = c >> 5;                                               \
                int bn = (c & 31) * 4;                                         \
                unsigned bs = sB_u + ((ST) * BSTG + bk * 136 + bn) * 4;        \
                cp16(bs, B + (long long)((K0) + bk) * ldb + n0 + bn, true);    \
            }                                                                  \
        }                                                                      \
    }

    const int KT = K / 32;
    ISSUE_COPY(0, 0);
    cp_commit();

    const unsigned* Asmu = (const unsigned*)Asm;
    const unsigned* Bsmu = (const unsigned*)Bsm;

    for (int it = 0; it < KT; it++) {
        cp_wait0();
        __syncthreads();
        if (it + 1 < KT) ISSUE_COPY((it + 1) & 1, (it + 1) * 32);
        cp_commit();

        const float*    As   = Asm  + (it & 1) * ASTG;
        const unsigned* Asu  = Asmu + (it & 1) * ASTG;
        const unsigned* Bsu  = Bsmu + (it & 1) * BSTG;

        #pragma unroll
        for (int ks = 0; ks < 4; ks++) {
            int k0f = ks * 8 + t4;
            unsigned afr[4][4], bfr[8][2];
            #pragma unroll
            for (int mi = 0; mi < 4; mi++) {
                int mr = wm + mi * 16 + g;
                if (RA) {
                    afr[mi][0] = f2tf(As[mr * ASTRIDE + k0f]);
                    afr[mi][1] = f2tf(As[(mr + 8) * ASTRIDE + k0f]);
                    afr[mi][2] = f2tf(As[mr * ASTRIDE + k0f + 4]);
                    afr[mi][3] = f2tf(As[(mr + 8) * ASTRIDE + k0f + 4]);
                } else {
                    afr[mi][0] = Asu[mr * ASTRIDE + k0f];
                    afr[mi][1] = Asu[(mr + 8) * ASTRIDE + k0f];
                    afr[mi][2] = Asu[mr * ASTRIDE + k0f + 4];
                    afr[mi][3] = Asu[(mr + 8) * ASTRIDE + k0f + 4];
                }
            }
            #pragma unroll
            for (int ni = 0; ni < 8; ni++) {
                int nc = wn + ni * 8 + g;
                if (TB) {
                    bfr[ni][0] = Bsu[nc * ASTRIDE + k0f];
                    bfr[ni][1] = Bsu[nc * ASTRIDE + k0f + 4];
                } else {
                    bfr[ni][0] = Bsu[k0f * 136 + nc];
                    bfr[ni][1] = Bsu[(k0f + 4) * 136 + nc];
                }
            }
            #pragma unroll
            for (int mi = 0; mi < 4; mi++)
                #pragma unroll
                for (int ni = 0; ni < 8; ni++)
                    mma_tf32(acc[mi][ni], afr[mi], bfr[ni]);
        }
        __syncthreads();
    }
#undef ISSUE_COPY

    if (EPI & EPI_GRAM) {
        sdiag[t] = 0.f;
        sdiag[t + 128] = 0.f;
        __syncthreads();
        #pragma unroll
        for (int mi = 0; mi < 4; mi++) {
            #pragma unroll
            for (int ni = 0; ni < 8; ni++) {
                int li0 = wm + mi * 16 + g;
                int lj0 = wn + ni * 8 + t4 * 2;
                #pragma unroll
                for (int half = 0; half < 2; half++) {
                    int li = li0 + half * 8;
                    atomicAdd(&sdiag[li - lj0 + 127],     acc[mi][ni][half * 2 + 0]);
                    atomicAdd(&sdiag[li - (lj0+1) + 127], acc[mi][ni][half * 2 + 1]);
                }
            }
        }
        __syncthreads();
        for (int i = t; i < 255; i += 128) {
            int tau = (m0 - n0 - 127 + i) & (LLEN - 1);
            atomicAdd(&C[tau], sdiag[i]);
        }
        return;
    }

    #pragma unroll
    for (int mi = 0; mi < 4; mi++) {
        #pragma unroll
        for (int ni = 0; ni < 8; ni++) {
            long long row0 = m0 + wm + mi * 16 + g;
            int col0 = n0 + wn + ni * 8 + t4 * 2;
            #pragma unroll
            for (int half = 0; half < 2; half++) {
                long long gm = row0 + half * 8;
                float v0 = acc[mi][ni][half * 2 + 0];
                float v1 = acc[mi][ni][half * 2 + 1];
                if (EPI & EPI_BIAS) { v0 += bias[col0]; v1 += bias[col0 + 1]; }
                if (EPI & EPI_RELU) { v0 = fmaxf(v0, 0.f); v1 = fmaxf(v1, 0.f); }
                if (EPI & EPI_GELU) {
                    v0 = 0.5f * v0 * (1.f + erff(v0 * 0.70710678118654752f));
                    v1 = 0.5f * v1 * (1.f + erff(v1 * 0.70710678118654752f));
                }
                if (EPI & EPI_RES) {
                    v0 += res[gm * N + col0];
                    v1 += res[gm * N + col0 + 1];
                }
                if (EPI & EPI_RND) { v0 = f2tf_f(v0); v1 = f2tf_f(v1); }
                if (EPI & EPI_RNDQK) {
                    if (col0 < 512) { v0 = f2tf_f(v0); v1 = f2tf_f(v1); }
                }
                *(float2*)(C + gm * N + col0) = make_float2(v0, v1);
            }
        }
    }
}

// one-shot tf32 round-copy of Wo / Wff1 / Wff2
__global__ void rnd3_kernel(const float* __restrict__ s0, float* __restrict__ d0, int n0,
                            const float* __restrict__ s1, float* __restrict__ d1, int n1,
                            const float* __restrict__ s2, float* __restrict__ d2, int n2)
{
    int total = n0 + n1 + n2;
    for (int i = blockIdx.x * 256 + threadIdx.x; i < total; i += gridDim.x * 256) {
        if (i < n0)            d0[i] = f2tf_f(s0[i]);
        else if (i < n0 + n1)  d1[i - n0] = f2tf_f(s1[i - n0]);
        else                   d2[i - n0 - n1] = f2tf_f(s2[i - n0 - n1]);
    }
}

// transpose conv2 weights [D=256][C=256][3] -> [K=768 (j*256+c)][D=256], rounded
__global__ void w2t_kernel(const float* __restrict__ w, float* __restrict__ o)
{
    int i = blockIdx.x * 256 + threadIdx.x;
    int d  = i & 255;
    int kk = i >> 8;
    int c  = kk & 255;
    int j  = kk >> 8;
    o[(long long)kk * 256 + d] = f2tf_f(w[(long long)d * 768 + c * 3 + j]);
}

// pack QKV weights: [lay][K=256][N=768] where N segment 0/1/2 = Wq/Wk/Wv, rounded
__global__ void packqkv_kernel(
    const float* __restrict__ Wq, const float* __restrict__ Wk,
    const float* __restrict__ Wv, const float* __restrict__ bq,
    const float* __restrict__ bk, const float* __restrict__ bv,
    float* __restrict__ wout, float* __restrict__ bout)
{
    long long i = (long long)blockIdx.x * 256 + threadIdx.x;   // NLAY*256*768
    int lay = (int)(i / 196608);
    int j   = (int)(i - (long long)lay * 196608);
    int k   = j / 768;
    int n   = j - k * 768;
    int seg = n >> 8, col = n & 255;
    const float* W = (seg == 0) ? Wq : (seg == 1) ? Wk : Wv;
    wout[i] = f2tf_f(W[(long long)lay * 65536 + k * 256 + col]);
    if (j < 768) {
        const float* bb = (seg == 0) ? bq : (seg == 1) ? bk : bv;
        bout[lay * 768 + j] = bb[lay * 256 + col];
    }
}

// =====================================================================
// split-K projection: emb[64][256] += x_enc[64][16384] @ proj_w[16384][256]
// grid (4 n-tiles, 64 K-chunks of 256); atomicAdd partials into zeroed emb.
// =====================================================================
__global__ __launch_bounds__(256) void proj_split_kernel(
    const float* __restrict__ A, const float* __restrict__ B, float* __restrict__ C)
{
    __shared__ float As[16][64];
    __shared__ float Bs[16][64];
    int n0 = blockIdx.x * 64;
    int kbase = blockIdx.y * 256;
    int t = threadIdx.x;
    int tx = t & 15, ty = t >> 4;
    float acc[4][4];
    #pragma unroll
    for (int i = 0; i < 4; i++)
        #pragma unroll
        for (int j = 0; j < 4; j++) acc[i][j] = 0.f;

    const int am = t >> 2, ak = (t & 3) * 4;
    const int bk = t >> 4, bn = (t & 15) * 4;

    for (int k0 = kbase; k0 < kbase + 256; k0 += 16) {
        float4 av = *(const float4*)(A + (long long)am * (LLEN * CIN) + k0 + ak);
        As[ak + 0][am] = av.x; As[ak + 1][am] = av.y;
        As[ak + 2][am] = av.z; As[ak + 3][am] = av.w;
        *(float4*)&Bs[bk][bn] = *(const float4*)(B + (long long)(k0 + bk) * HSZ + n0 + bn);
        __syncthreads();
        #pragma unroll
        for (int kk = 0; kk < 16; kk++) {
            float4 a4 = *(const float4*)&As[kk][ty * 4];
            float4 b4 = *(const float4*)&Bs[kk][tx * 4];
            float a[4] = {a4.x, a4.y, a4.z, a4.w};
            float b[4] = {b4.x, b4.y, b4.z, b4.w};
            #pragma unroll
            for (int i = 0; i < 4; i++)
                #pragma unroll
                for (int j = 0; j < 4; j++)
                    acc[i][j] += a[i] * b[j];
        }
        __syncthreads();
    }
    #pragma unroll
    for (int i = 0; i < 4; i++)
        #pragma unroll
        for (int j = 0; j < 4; j++)
            atomicAdd(&C[(long long)(ty * 4 + i) * HSZ + n0 + tx * 4 + j], acc[i][j]);
}

// 64x64x16 fp32 tile version for small-M GEMMs (M=64). B is [K,N] only.
template<int EPI>
__global__ __launch_bounds__(256) void sgemm64(
    const float* __restrict__ A, const float* __restrict__ B,
    const float* __restrict__ bias, float* __restrict__ C,
    int M, int N, int K)
{
    __shared__ float As[16][64];
    __shared__ float Bs[16][64];
    int m0 = blockIdx.y * 64, n0 = blockIdx.x * 64;
    int t = threadIdx.x;
    int tx = t & 15, ty = t >> 4;
    float acc[4][4];
    #pragma unroll
    for (int i = 0; i < 4; i++)
        #pragma unroll
        for (int j = 0; j < 4; j++) acc[i][j] = 0.f;

    const int am = t >> 2, ak = (t & 3) * 4;
    const int bk = t >> 4, bn = (t & 15) * 4;

    for (int k0 = 0; k0 < K; k0 += 16) {
        float4 av = *(const float4*)(A + (long long)(m0 + am) * K + k0 + ak);
        As[ak + 0][am] = av.x; As[ak + 1][am] = av.y;
        As[ak + 2][am] = av.z; As[ak + 3][am] = av.w;
        *(float4*)&Bs[bk][bn] = *(const float4*)(B + (long long)(k0 + bk) * N + n0 + bn);
        __syncthreads();
        #pragma unroll
        for (int kk = 0; kk < 16; kk++) {
            float4 a4 = *(const float4*)&As[kk][ty * 4];
            float4 b4 = *(const float4*)&Bs[kk][tx * 4];
            float a[4] = {a4.x, a4.y, a4.z, a4.w};
            float b[4] = {b4.x, b4.y, b4.z, b4.w};
            #pragma unroll
            for (int i = 0; i < 4; i++)
                #pragma unroll
                for (int j = 0; j < 4; j++)
                    acc[i][j] += a[i] * b[j];
        }
        __syncthreads();
    }
    #pragma unroll
    for (int i = 0; i < 4; i++) {
        long long gm = m0 + ty * 4 + i;
        float vr[4];
        #pragma unroll
        for (int j = 0; j < 4; j++) {
            int gn = n0 + tx * 4 + j;
            float v = acc[i][j];
            if (EPI & EPI_BIAS) v += bias[gn];
            if (EPI & EPI_RELU) v = fmaxf(v, 0.f);
            vr[j] = v;
        }
        *(float4*)(C + gm * N + n0 + tx * 4) = make_float4(vr[0], vr[1], vr[2], vr[3]);
    }
}

// =====================================================================
// conv1: [B,L,16] -> relu(conv1d k=3 pad=1) -> [B,L,256] (tf32-rounded)
// =====================================================================
__global__ __launch_bounds__(256) void conv1_kernel(
    const float* __restrict__ x, const float* __restrict__ w,
    const float* __restrict__ bias, float* __restrict__ out)
{
    int b = blockIdx.y, l0 = blockIdx.x * 16, d = threadIdx.x;
    __shared__ float sx[18][16];
    for (int idx = d; idx < 18 * 16; idx += 256) {
        int r = idx >> 4, c = idx & 15;
        int ll = l0 - 1 + r;
        sx[r][c] = (ll >= 0 && ll < LLEN) ? x[((long long)b * LLEN + ll) * CIN + c] : 0.f;
    }
    __syncthreads();
    float wreg[48];
    #pragma unroll
    for (int i = 0; i < 48; i++) wreg[i] = w[d * 48 + i];
    float bd = bias[d];
    #pragma unroll 4
    for (int i = 0; i < 16; i++) {
        float acc = bd;
        #pragma unroll
        for (int c = 0; c < 16; c++)
            #pragma unroll
            for (int j = 0; j < 3; j++)
                acc += sx[i + j][c] * wreg[c * 3 + j];
        out[((long long)b * LLEN + l0 + i) * DD + d] = f2tf_f(fmaxf(acc, 0.f));
    }
}

// =====================================================================
// LayerNorm over last dim = 256. 8 rows/block, 32 lanes/row, shuffle.
// PRERELU: x = relu(in + pb) before normalization (for split-K proj path).
// =====================================================================
template<bool PRERELU>
__global__ __launch_bounds__(256) void ln256_kernel(
    const float* __restrict__ in, const float* __restrict__ g,
    const float* __restrict__ bt, const float* __restrict__ pb,
    float* __restrict__ out, long long ostride, long long ooff)
{
    int t = threadIdx.x;
    int lane = t & 31, wr = t >> 5;
    long long r = (long long)blockIdx.x * 8 + wr;
    const float* ip = in + r * 256 + lane * 8;
    float4 v0 = *(const float4*)ip;
    float4 v1 = *(const float4*)(ip + 4);
    float x[8] = {v0.x, v0.y, v0.z, v0.w, v1.x, v1.y, v1.z, v1.w};
    if (PRERELU) {
        float4 p0 = *(const float4*)(pb + lane * 8);
        float4 p1 = *(const float4*)(pb + lane * 8 + 4);
        float pp[8] = {p0.x, p0.y, p0.z, p0.w, p1.x, p1.y, p1.z, p1.w};
        #pragma unroll
        for (int j = 0; j < 8; j++) x[j] = fmaxf(x[j] + pp[j], 0.f);
    }
    float s = 0.f;
    #pragma unroll
    for (int j = 0; j < 8; j++) s += x[j];
    #pragma unroll
    for (int o = 16; o; o >>= 1) s += __shfl_xor_sync(0xFFFFFFFFu, s, o);
    float mean = s * (1.f / 256.f);
    float vs = 0.f;
    #pragma unroll
    for (int j = 0; j < 8; j++) { x[j] -= mean; vs += x[j] * x[j]; }
    #pragma unroll
    for (int o = 16; o; o >>= 1) vs += __shfl_xor_sync(0xFFFFFFFFu, vs, o);
    float inv = rsqrtf(vs * (1.f / 256.f) + 1e-5f);
    float4 g0 = *(const float4*)(g + lane * 8);
    float4 g1 = *(const float4*)(g + lane * 8 + 4);
    float4 b0 = *(const float4*)(bt + lane * 8);
    float4 b1 = *(const float4*)(bt + lane * 8 + 4);
    float gg[8] = {g0.x, g0.y, g0.z, g0.w, g1.x, g1.y, g1.z, g1.w};
    float bb[8] = {b0.x, b0.y, b0.z, b0.w, b1.x, b1.y, b1.z, b1.w};
    float o8[8];
    #pragma unroll
    for (int j = 0; j < 8; j++) o8[j] = x[j] * inv * gg[j] + bb[j];
    float* op = out + r * ostride + ooff + lane * 8;
    *(float4*)op       = make_float4(o8[0], o8[1], o8[2], o8[3]);
    *(float4*)(op + 4) = make_float4(o8[4], o8[5], o8[6], o8[7]);
}

// =====================================================================
// top-k(20) + softmax (ties -> lowest index, matches lax.top_k)
// =====================================================================
__global__ __launch_bounds__(256) void topk_kernel(
    const float* __restrict__ rp, int* __restrict__ del, float* __restrict__ wts)
{
    int b = blockIdx.x, t = threadIdx.x;
    __shared__ float sv[LLEN];
    __shared__ float rv[256];
    __shared__ int   ri[256];
    __shared__ float selv[TOPK];
    __shared__ int   seli[TOPK];
    for (int i = t; i < LLEN; i += 256)
        sv[i] = rp[(long long)b * LLEN + i] * (1.f / 256.f);
    __syncthreads();
    for (int iter = 0; iter < TOPK; iter++) {
        float bv = -INFINITY; int bi = 1 << 30;
        for (int i = t; i < LLEN; i += 256) {
            float v = sv[i];
            if (v > bv || (v == bv && i < bi)) { bv = v; bi = i; }
        }
        rv[t] = bv; ri[t] = bi; __syncthreads();
        for (int s = 128; s > 0; s >>= 1) {
            if (t < s) {
                if (rv[t + s] > rv[t] || (rv[t + s] == rv[t] && ri[t + s] < ri[t])) {
                    rv[t] = rv[t + s]; ri[t] = ri[t + s];
                }
            }
            __syncthreads();
        }
        if (t == 0) { selv[iter] = rv[0]; seli[iter] = ri[0]; sv[ri[0]] = -INFINITY; }
        __syncthreads();
    }
    if (t == 0) {
        float m = selv[0];
        float e[TOPK], ssum = 0.f;
        for (int k2 = 0; k2 < TOPK; k2++) { e[k2] = expf(selv[k2] - m); ssum += e[k2]; }
        float inv = 1.f / ssum;
        for (int k2 = 0; k2 < TOPK; k2++) {
            wts[b * TOPK + k2] = e[k2] * inv;
            del[b * TOPK + k2] = seli[k2];
        }
    }
}

// =====================================================================
// delayed aggregation: out[b,l,d] = sum_k w[k] * V[b,(l+delay[k])%L,d]
// V = qkv + 512, row stride 768. Output tf32-rounded (feeds only Wo GEMM A).
// =====================================================================
__global__ __launch_bounds__(256) void agg_kernel(
    const float* __restrict__ QKV, const int* __restrict__ del,
    const float* __restrict__ wts, float* __restrict__ out)
{
    int t = threadIdx.x;
    int b = blockIdx.y;
    int l = blockIdx.x * 4 + (t >> 6);
    int d4 = (t & 63) * 4;
    __shared__ int   sd[TOPK];
    __shared__ float sw[TOPK];
    if (t < TOPK) { sd[t] = del[b * TOPK + t]; sw[t] = wts[b * TOPK + t]; }
    __syncthreads();
    const float* vb = QKV + (long long)b * LLEN * 768 + 512;
    float a0 = 0.f, a1 = 0.f, a2 = 0.f, a3 = 0.f;
    #pragma unroll
    for (int k2 = 0; k2 < TOPK; k2++) {
        float w = sw[k2];
        float4 v = *(const float4*)(vb + (long long)((l + sd[k2]) & (LLEN - 1)) * 768 + d4);
        a0 += w * v.x; a1 += w * v.y; a2 += w * v.z; a3 += w * v.w;
    }
    *(float4*)(out + ((long long)b * LLEN + l) * DD + d4) =
        make_float4(f2tf_f(a0), f2tf_f(a1), f2tf_f(a2), f2tf_f(a3));
}

// =====================================================================
// series decomposition: out = in - movavg25(in, replicate-pad).
// If fin != nullptr, also writes the l=1023 row into fin[b][off..off+255]
// (fused pooled-feature copy).
// =====================================================================
__global__ __launch_bounds__(256) void decomp_kernel(
    const float* __restrict__ in, float* __restrict__ out,
    float* __restrict__ fin, int off)
{
    __shared__ float s[88][65];
    int b  = blockIdx.z;
    int c0 = blockIdx.y * 64;
    int l0 = blockIdx.x * 64;
    int t  = threadIdx.x;
    const float* base = in + (long long)b * LLEN * DD;
    for (int idx = t; idx < 88 * 64; idx += 256) {
        int r = idx >> 6, c = idx & 63;
        int ll = l0 - 12 + r;
        ll = max(0, min(LLEN - 1, ll));
        s[r][c] = base[(long long)ll * DD + c0 + c];
    }
    __syncthreads();
    int c = t & 63, lg = t >> 6;
    int lbase = lg * 16;
    float sum = 0.f;
    #pragma unroll
    for (int r = 0; r < MAW; r++) sum += s[lbase + r][c];
    float* ob = out + (long long)b * LLEN * DD;
    float v = s[lbase + 12][c] - sum * (1.f / MAW);
    ob[(long long)(l0 + lbase) * DD + c0 + c] = v;
    if (fin && (l0 + lbase) == LLEN - 1)
        fin[b * (NLAY * DD + HSZ) + off + c0 + c] = v;
    #pragma unroll
    for (int i = 1; i < 16; i++) {
        sum += s[lbase + i + 24][c] - s[lbase + i - 1][c];
        v = s[lbase + i + 12][c] - sum * (1.f / MAW);
        ob[(long long)(l0 + lbase + i) * DD + c0 + c] = v;
        if (fin && (l0 + lbase + i) == LLEN - 1)
            fin[b * (NLAY * DD + HSZ) + off + c0 + c] = v;
    }
}

__global__ __launch_bounds__(256) void rp2_kernel(
    const float* __restrict__ o2, const float* __restrict__ w,
    const float* __restrict__ bias, float* __restrict__ out)
{
    int b = blockIdx.x, t = threadIdx.x;
    __shared__ float red[256];
    red[t] = o2[b * 256 + t] * w[t];
    __syncthreads();
    for (int s = 128; s > 0; s >>= 1) { if (t < s) red[t] += red[t + s]; __syncthreads(); }
    if (t == 0) out[b] = red[0] + bias[0];
}

// =====================================================================
// launch
// =====================================================================
extern "C" void kernel_launch(void* const* d_in, const int* in_sizes, int n_in,
                              void* d_out, int out_size)
{
    (void)in_sizes; (void)n_in; (void)out_size;
    const float* x_enc     = (const float*)d_in[0];
    const float* conv1_w   = (const float*)d_in[1];
    const float* conv1_b   = (const float*)d_in[2];
    const float* conv2_w   = (const float*)d_in[3];
    const float* conv2_b   = (const float*)d_in[4];
    const float* cnn_ln_g  = (const float*)d_in[5];
    const float* cnn_ln_b  = (const float*)d_in[6];
    const float* proj_w    = (const float*)d_in[7];
    const float* proj_b    = (const float*)d_in[8];
    const float* proj_ln_g = (const float*)d_in[9];
    const float* proj_ln_b = (const float*)d_in[10];
    const float* Wq        = (const float*)d_in[11];
    const float* bq        = (const float*)d_in[12];
    const float* Wk        = (const float*)d_in[13];
    const float* bk        = (const float*)d_in[14];
    const float* Wv        = (const float*)d_in[15];
    const float* bv        = (const float*)d_in[16];
    const float* Wo        = (const float*)d_in[17];
    const float* bo        = (const float*)d_in[18];
    const float* Wff1      = (const float*)d_in[19];
    const float* Wff2      = (const float*)d_in[20];
    const float* rp1_w     = (const float*)d_in[21];
    const float* rp1_b     = (const float*)d_in[22];
    const float* rp_ln_g   = (const float*)d_in[23];
    const float* rp_ln_b   = (const float*)d_in[24];
    const float* rp2_w     = (const float*)d_in[25];
    const float* rp2_b     = (const float*)d_in[26];
    float* out = (float*)d_out;

    float *p_h1, *p_enc, *p_qkv, *p_ac, *p_xs, *p_xd, *p_big, *p_rp;
    float *p_emb, *p_final, *p_o1, *p_o2, *p_w, *p_w2t, *p_wqkv, *p_bqkv;
    float *p_wo, *p_wf1, *p_wf2;
    int* p_del;
    cudaGetSymbolAddress((void**)&p_h1,  g_h1);
    cudaGetSymbolAddress((void**)&p_enc, g_enc);
    cudaGetSymbolAddress((void**)&p_qkv, g_qkv);
    cudaGetSymbolAddress((void**)&p_ac,  g_ac);
    cudaGetSymbolAddress((void**)&p_xs,  g_xs);
    cudaGetSymbolAddress((void**)&p_xd,  g_xd);
    cudaGetSymbolAddress((void**)&p_big, g_big);
    cudaGetSymbolAddress((void**)&p_rp,  g_rp);
    cudaGetSymbolAddress((void**)&p_del, g_del);
    cudaGetSymbolAddress((void**)&p_w,   g_w);
    cudaGetSymbolAddress((void**)&p_emb, g_emb);
    cudaGetSymbolAddress((void**)&p_final, g_final);
    cudaGetSymbolAddress((void**)&p_o1,  g_o1);
    cudaGetSymbolAddress((void**)&p_o2,  g_o2);
    cudaGetSymbolAddress((void**)&p_w2t, g_w2t);
    cudaGetSymbolAddress((void**)&p_wqkv, g_wqkv);
    cudaGetSymbolAddress((void**)&p_bqkv, g_bqkv);
    cudaGetSymbolAddress((void**)&p_wo,  g_wo_r);
    cudaGetSymbolAddress((void**)&p_wf1, g_wf1_r);
    cudaGetSymbolAddress((void**)&p_wf2, g_wf2_r);

    const int MBL = BB * LLEN;  // 65536
    const long long SLD = (long long)LLEN * DD;
    const long long SLQ = (long long)LLEN * 768;

    // opt-in to 72KB dynamic smem for every tgemm instantiation
    cudaFuncSetAttribute(tgemm128<1, false, EPI_BIAS | EPI_RELU, false>, cudaFuncAttributeMaxDynamicSharedMemorySize, TG_DYN_BYTES);
    cudaFuncSetAttribute(tgemm128<0, false, EPI_BIAS | EPI_RNDQK, true>, cudaFuncAttributeMaxDynamicSharedMemorySize, TG_DYN_BYTES);
    cudaFuncSetAttribute(tgemm128<0, true,  EPI_GRAM, false>,            cudaFuncAttributeMaxDynamicSharedMemorySize, TG_DYN_BYTES);
    cudaFuncSetAttribute(tgemm128<0, false, EPI_BIAS | EPI_RES, false>,  cudaFuncAttributeMaxDynamicSharedMemorySize, TG_DYN_BYTES);
    cudaFuncSetAttribute(tgemm128<0, true,  EPI_GELU | EPI_RND, true>,   cudaFuncAttributeMaxDynamicSharedMemorySize, TG_DYN_BYTES);
    cudaFuncSetAttribute(tgemm128<0, true,  EPI_RES, false>,             cudaFuncAttributeMaxDynamicSharedMemorySize, TG_DYN_BYTES);

    // prep + frontend
    w2t_kernel<<<768, 256>>>(conv2_w, p_w2t);
    packqkv_kernel<<<NLAY * 768, 256>>>(Wq, Wk, Wv, bq, bk, bv, p_wqkv, p_bqkv);
    rnd3_kernel<<<2048, 256>>>(Wo, p_wo, NLAY * 256 * 256,
                               Wff1, p_wf1, NLAY * DFF * 256,
                               Wff2, p_wf2, NLAY * 256 * DFF);
    cudaMemsetAsync(p_emb, 0, (size_t)BB * HSZ * sizeof(float));
    proj_split_kernel<<<dim3(4, 64), 256>>>(x_enc, proj_w, p_emb);
    conv1_kernel<<<dim3(LLEN / 16, BB), 256>>>(x_enc, conv1_w, conv1_b, p_h1);
    tgemm128<1, false, EPI_BIAS | EPI_RELU, false><<<dim3(2, 8, BB), 128, TG_DYN_BYTES>>>(
        p_h1, p_w2t, conv2_b, nullptr, p_xs, LLEN, DD, 768, 256, 256, SLD, 0, SLD);
    ln256_kernel<false><<<MBL / 8, 256>>>(p_xs, cnn_ln_g, cnn_ln_b, nullptr, p_enc, 256, 0);

    for (int i = 0; i < NLAY; i++) {
        const float* Wo_i  = p_wo  + (long long)i * DD * DD;
        const float* Wf1_i = p_wf1 + (long long)i * DFF * DD;
        const float* Wf2_i = p_wf2 + (long long)i * DD * DFF;
        const float* bo_i = bo + i * DD;

        // fused QKV projection; Q,K columns tf32-rounded at store (feed only Gram)
        tgemm128<0, false, EPI_BIAS | EPI_RNDQK, true><<<dim3(6, 512, 1), 128, TG_DYN_BYTES>>>(
            p_enc, p_wqkv + (long long)i * 196608, p_bqkv + i * 768, nullptr,
            p_qkv, MBL, 768, 256, 256, 768, 0, 0, 0);

        // fused Gram + wrapped-diagonal reduction -> rp[b][tau]
        cudaMemsetAsync(p_rp, 0, (size_t)BB * LLEN * sizeof(float));
        tgemm128<0, true, EPI_GRAM, false><<<dim3(8, 8, BB), 128, TG_DYN_BYTES>>>(
            p_qkv, p_qkv + 256, nullptr, nullptr, p_rp,
            LLEN, LLEN, 256, 768, 768, SLQ, SLQ, LLEN);
        topk_kernel<<<BB, 256>>>(p_rp, p_del, p_w);
        agg_kernel<<<dim3(LLEN / 4, BB), 256>>>(p_qkv, p_del, p_w, p_ac);

        // x = enc + (ac @ Wo + bo)
        tgemm128<0, false, EPI_BIAS | EPI_RES, false><<<dim3(2, 512, 1), 128, TG_DYN_BYTES>>>(
            p_ac, Wo_i, bo_i, p_enc, p_xs, MBL, DD, DD, 256, 256, 0, 0, 0);
        decomp_kernel<<<dim3(16, 4, BB), 256>>>(p_xs, p_xd, nullptr, 0);

        // FFN (tf32 TC); FFN1 output rounded (feeds only FFN2 A-side)
        tgemm128<0, true, EPI_GELU | EPI_RND, true><<<dim3(8, 512, 1), 128, TG_DYN_BYTES>>>(
            p_xd, Wf1_i, nullptr, nullptr, p_big, MBL, DFF, DD, 256, 256, 0, 0, 0);
        tgemm128<0, true, EPI_RES, false><<<dim3(2, 512, 1), 128, TG_DYN_BYTES>>>(
            p_big, Wf2_i, nullptr, p_xd, p_xs, MBL, DD, DFF, 1024, 1024, 0, 0, 0);
        // decomp fused with pooled-feature copy of the last timestep
        decomp_kernel<<<dim3(16, 4, BB), 256>>>(p_xs, p_enc, p_final, i * DD);
    }

    // input embed: bias+relu+LN fused (split-K partials in p_emb)
    ln256_kernel<true><<<BB / 8, 256>>>(p_emb, proj_ln_g, proj_ln_b, proj_b,
                                        p_final, NLAY * DD + HSZ, NLAY * DD);

    // regression head
    sgemm64<EPI_BIAS | EPI_RELU><<<dim3(4, 1), 256>>>(p_final, rp1_w, rp1_b, p_o1, BB, HSZ, NLAY * DD + HSZ);
    ln256_kernel<false><<<BB / 8, 256>>>(p_o1, rp_ln_g, rp_ln_b, nullptr, p_o2, 256, 0);
    rp2_kernel<<<BB, 256>>>(p_o2, rp2_w, rp2_b, out);
}